// round 12
// baseline (speedup 1.0000x reference)
#include <cuda_runtime.h>
#include <cuda_fp16.h>
#include <math.h>
#include <stdint.h>

#define BB      2
#define NNODES  512
#define NCGC    64
#define FDIM    128
#define NRBF    20
#define NCONVS  3
#define ETOT    32768
#define BN      (BB*NNODES)      // 1024
#define CUT     5.0f
#define PI_F    3.14159265358979323846f
#define PMSG    4096
#define PCON    1024
#define DMAXC   10.0f

// ---------------- persistent device scratch ----------------
__device__ float  g_h[2][BN*FDIM];
__device__ float4 g_v[2][BN*FDIM];
__device__ float4 g_phi4[BN*FDIM];            // (phi_e0, phi_e1, phi_e2, 0) per (node,f)
__device__ float  g_phic[BN*384];
__device__ float4 g_TmsgA[NCONVS*PMSG*FDIM];  // (w0[p], w0[p+1], w1[p], w1[p+1])
__device__ float2 g_TmsgB[NCONVS*PMSG*FDIM];  // (w2[p], w2[p+1])
__device__ __half2 g_TconH[NCONVS*PCON*384];  // fp16 pair-packed: (v[p], v[p+1])
__device__ float  g_ed[ETOT];
__device__ float4 g_un[ETOT];
__device__ int    g_pi[ETOT], g_pj[ETOT];
__device__ int    g_ptrn[BN+1];
__device__ int    g_csr[ETOT];

__device__ __forceinline__ float silu(float x) { return x / (1.f + expf(-x)); }

#define CP_COMMIT() asm volatile("cp.async.commit_group;" ::: "memory")
#define CP_WAIT(n)  asm volatile("cp.async.wait_group %0;" :: "n"(n) : "memory")

// contiguous 64KB (4096 float4) global -> smem via cp.async, 512 threads
__device__ __forceinline__ void stage64(uint32_t sdst, const float4* __restrict__ src, int t)
{
    #pragma unroll
    for (int j = 0; j < 8; j++) {
        int i = t + j*512;
        asm volatile("cp.async.cg.shared.global [%0], [%1], 16;"
                     :: "r"(sdst + i*16), "l"(src + i) : "memory");
    }
}
// W2 chunk mm (128 rows x 128 cols out of 384-col rows) -> smem, 512 threads
__device__ __forceinline__ void stageW2(uint32_t sdst, const float4* __restrict__ W2_4, int mm, int t)
{
    #pragma unroll
    for (int j = 0; j < 8; j++) {
        int i = t + j*512;
        int k = i >> 5, c = i & 31;
        asm volatile("cp.async.cg.shared.global [%0], [%1], 16;"
                     :: "r"(sdst + i*16), "l"(W2_4 + k*96 + mm*32 + c) : "memory");
    }
}

// GEMV pair: out column g for nodes n0, n0+1, weights in BUF, input IN
#define GEMV2(BUF, IN, a0, a1) \
    _Pragma("unroll 8") \
    for (int k_ = 0; k_ < FDIM; k_ += 4) { \
        float4 h0_ = *(const float4*)&IN[n0*FDIM + k_]; \
        float4 h1_ = *(const float4*)&IN[(n0+1)*FDIM + k_]; \
        float w0_ = BUF[k_*FDIM+g], w1_ = BUF[(k_+1)*FDIM+g]; \
        float w2_ = BUF[(k_+2)*FDIM+g], w3_ = BUF[(k_+3)*FDIM+g]; \
        a0 += h0_.x*w0_ + h0_.y*w1_ + h0_.z*w2_ + h0_.w*w3_; \
        a1 += h1_.x*w0_ + h1_.y*w1_ + h1_.z*w2_ + h1_.w*w3_; \
    }

// ---------------- init (h/v/out) + edge geometry, fused ----------------
__global__ void k_init_geom(const float* __restrict__ h_in, const float* __restrict__ H_in,
                            float* __restrict__ out,
                            const int* __restrict__ nbr, const float* __restrict__ xyz)
{
    int idx = blockIdx.x*blockDim.x + threadIdx.x;   // 32768 threads exactly
    {
        int e = idx;
        int b  = nbr[3*e], ii = nbr[3*e+1], jj = nbr[3*e+2];
        int pi = b*NNODES + ii, pj = b*NNODES + jj;
        g_pi[e] = pi; g_pj[e] = pj;
        float rx = xyz[3*pi]   - xyz[3*pj];
        float ry = xyz[3*pi+1] - xyz[3*pj+1];
        float rz = xyz[3*pi+2] - xyz[3*pj+2];
        float d = sqrtf(rx*rx + ry*ry + rz*rz);
        g_ed[e] = d;
        float inv = 1.f/d;
        g_un[e] = make_float4(rx*inv, ry*inv, rz*inv, 0.f);
    }
    for (int i = idx; i < BN*FDIM; i += ETOT) {
        g_h[0][i] = h_in[i];
        g_v[0][i] = make_float4(0.f,0.f,0.f,0.f);
    }
    for (int i = idx; i < BB*NCGC*FDIM*4; i += ETOT)
        out[i] = (i < BB*NCGC*FDIM) ? H_in[i] : 0.f;
}

// ---------------- count + scan + CSR fill, one block, smem counters ----------------
__global__ void k_scan_fill()
{
    __shared__ int s_cnt[BN];
    __shared__ int s_scan[BN];
    __shared__ int s_fill[BN];
    int t = threadIdx.x;   // 1024
    s_cnt[t] = 0;
    __syncthreads();
    for (int e = t; e < ETOT; e += BN)
        if (g_ed[e] < CUT) atomicAdd(&s_cnt[g_pi[e]], 1);
    __syncthreads();
    s_scan[t] = s_cnt[t];
    __syncthreads();
    for (int off = 1; off < BN; off <<= 1) {
        int x = (t >= off) ? s_scan[t-off] : 0;
        __syncthreads();
        s_scan[t] += x;
        __syncthreads();
    }
    g_ptrn[t+1] = s_scan[t];
    if (t == 0) g_ptrn[0] = 0;
    s_cnt[t] = s_scan[t] - s_cnt[t];
    s_fill[t] = 0;
    __syncthreads();
    for (int e = t; e < ETOT; e += BN) {
        if (g_ed[e] < CUT) {
            int pi = g_pi[e];
            int pos = s_cnt[pi] + atomicAdd(&s_fill[pi], 1);
            g_csr[pos] = e;
        }
    }
}

// ---------------- message table (pair-packed float4/float2, f-indexed) ----------------
__global__ void k_msg_table(const float* __restrict__ We, const float* __restrict__ be)
{
    int p = blockIdx.x, t = blockIdx.y, f = threadIdx.x; // 128 threads
    const float step = CUT/(PMSG-1);
    float d0 = p*step;
    int p1i = (p+1 < PMSG) ? p+1 : PMSG-1;
    float d1 = p1i*step;
    float env0 = (d0 < CUT) ? 0.5f*(cosf(PI_F*d0/CUT) + 1.f) : 0.f;
    float env1 = (d1 < CUT) ? 0.5f*(cosf(PI_F*d1/CUT) + 1.f) : 0.f;
    __shared__ float rb[2][NRBF];
    if (f < 2*NRBF) {
        int which = f/NRBF, k = f%NRBF;
        float d = which ? d1 : d0;
        float dd = fmaxf(d, 1e-6f);
        rb[which][k] = sinf((k+1)*PI_F/CUT*dd)/dd;
    }
    __syncthreads();
    const float* Wt = We + t*NRBF*384;
    const float* bt = be + t*384;
    float b0 = bt[f], b1 = bt[128+f], b2 = bt[256+f];
    float w0p0=b0, w0p1=b0, w1p0=b1, w1p1=b1, w2p0=b2, w2p1=b2;
    #pragma unroll
    for (int k = 0; k < NRBF; k++) {
        float wa = Wt[k*384+f], wb = Wt[k*384+128+f], wc = Wt[k*384+256+f];
        float r0 = rb[0][k], r1 = rb[1][k];
        w0p0 += r0*wa; w0p1 += r1*wa;
        w1p0 += r0*wb; w1p1 += r1*wb;
        w2p0 += r0*wc; w2p1 += r1*wc;
    }
    int o = (t*PMSG+p)*FDIM + f;
    g_TmsgA[o] = make_float4(w0p0*env0, w0p1*env1, w1p0*env0, w1p1*env1);
    g_TmsgB[o] = make_float2(w2p0*env0, w2p1*env1);
}

// ---------------- contraction table (fp16 pair-packed, columns remapped to [e3][f]) ----------------
__global__ void k_con_table(const float* __restrict__ Wf)
{
    __shared__ float es[17][FDIM];
    int tid = threadIdx.x;              // 384 threads
    int p0  = blockIdx.x*16, t = blockIdx.y;
    const float step = DMAXC/(PCON-1);
    for (int i = tid; i < 17*FDIM; i += 384) {
        int pl = i / FDIM, k = i % FDIM;
        float d = (p0+pl)*step;
        float o = CUT*k/127.f;
        float x = d - o;
        es[pl][k] = expf(-x*x);
    }
    __syncthreads();
    int src = (tid & 127)*3 + (tid >> 7);
    float acc[17];
    #pragma unroll
    for (int p = 0; p < 17; p++) acc[p] = 0.f;
    const float* Wt = Wf + t*FDIM*384;
    for (int k = 0; k < FDIM; k++) {
        float w = Wt[k*384 + src];
        #pragma unroll
        for (int p = 0; p < 17; p++) acc[p] += es[p][k]*w;
    }
    #pragma unroll
    for (int p = 0; p < 16; p++)
        g_TconH[(t*PCON + p0 + p)*384 + tid] = __floats2half2_rn(acc[p], acc[p+1]);
}

// ---------------- standalone MLP (msg t=0 only), R9 scalar form ----------------
// smem floats: wsW1[16384] | bufA[16384] | bufB[16384] | h_s[1024] | hid_s[1024] = 204800 B
__global__ void __launch_bounds__(512) k_mlp(int hsel,
                      const float* __restrict__ W1, const float* __restrict__ b1,
                      const float* __restrict__ W2, const float* __restrict__ b2, int dst_sel)
{
    extern __shared__ float sm[];
    uint32_t smb = (uint32_t)__cvta_generic_to_shared(sm);
    float* wsW1  = sm;
    float* bufA  = sm + 16384;
    float* bufB  = sm + 32768;
    float* h_s   = sm + 49152;
    float* hid_s = sm + 50176;
    int t = threadIdx.x;                // 512
    int nb = blockIdx.x*8;
    const float4* W2_4 = (const float4*)W2;

    stage64(smb,            (const float4*)W1, t); CP_COMMIT();
    stageW2(smb + 16384*4,  W2_4, 0, t);           CP_COMMIT();
    stageW2(smb + 32768*4,  W2_4, 1, t);           CP_COMMIT();
    const float* hb = g_h[hsel];
    for (int i = t; i < 8*FDIM; i += 512)
        h_s[i] = hb[nb*FDIM + i];

    CP_WAIT(2);
    __syncthreads();
    int g = t & 127, n0 = (t >> 7) * 2;
    {
        float a0 = b1[g], a1 = a0;
        GEMV2(wsW1, h_s, a0, a1)
        hid_s[n0*FDIM+g]     = silu(a0);
        hid_s[(n0+1)*FDIM+g] = silu(a1);
    }
    float A[3][2];
    CP_WAIT(1);
    __syncthreads();
    {
        float a0 = b2[g], a1 = a0;
        GEMV2(bufA, hid_s, a0, a1)
        A[0][0] = a0; A[0][1] = a1;
    }
    __syncthreads();
    stageW2(smb + 16384*4, W2_4, 2, t); CP_COMMIT();
    CP_WAIT(1);
    __syncthreads();
    {
        float a0 = b2[128+g], a1 = a0;
        GEMV2(bufB, hid_s, a0, a1)
        A[1][0] = a0; A[1][1] = a1;
    }
    CP_WAIT(0);
    __syncthreads();
    {
        float a0 = b2[256+g], a1 = a0;
        GEMV2(bufA, hid_s, a0, a1)
        A[2][0] = a0; A[2][1] = a1;
    }
    if (dst_sel == 0) {
        g_phi4[(nb+n0  )*FDIM + g] = make_float4(A[0][0], A[1][0], A[2][0], 0.f);
        g_phi4[(nb+n0+1)*FDIM + g] = make_float4(A[0][1], A[1][1], A[2][1], 0.f);
    } else {
        #pragma unroll
        for (int mm = 0; mm < 3; mm++) {
            int m = mm*128 + g;
            int oi = ((m % 3) << 7) + (m / 3);
            g_phic[(nb+n0  )*384 + oi] = A[mm][0];
            g_phic[(nb+n0+1)*384 + oi] = A[mm][1];
        }
    }
}

// ---------------- edge message pass: packed table + phi4 ----------------
__global__ void __launch_bounds__(128) k_edge(int t, int cur, int nxt)
{
    int i = blockIdx.x, f = threadIdx.x;
    int e0 = g_ptrn[i], e1 = g_ptrn[i+1];
    const float4* TA = g_TmsgA + (size_t)t*PMSG*FDIM;
    const float2* TB = g_TmsgB + (size_t)t*PMSG*FDIM;
    const float4* vcur = g_v[cur];
    const float inv_step = (PMSG-1)/CUT;
    float acch = 0.f, av0 = 0.f, av1 = 0.f, av2 = 0.f;
    for (int q = e0; q < e1; q++) {
        int e = g_csr[q];
        float d = g_ed[e];
        float u = d*inv_step;
        int idx = (int)u; if (idx > PMSG-2) idx = PMSG-2;
        float fr = u - idx;
        float4 Aq = TA[idx*FDIM + f];
        float2 Bq = TB[idx*FDIM + f];
        float w0 = fmaf(fr, Aq.y - Aq.x, Aq.x);
        float w1 = fmaf(fr, Aq.w - Aq.z, Aq.z);
        float w2 = fmaf(fr, Bq.y - Bq.x, Bq.x);
        int pj = g_pj[e];
        float4 ph = g_phi4[pj*FDIM + f];
        float i0 = ph.x*w0, i1 = ph.y*w1, i2 = ph.z*w2;
        float4 uq = g_un[e];
        float4 vj = vcur[pj*FDIM + f];
        acch += i1;
        av0  += i2*uq.x + i0*vj.x;
        av1  += i2*uq.y + i0*vj.y;
        av2  += i2*uq.z + i0*vj.z;
    }
    g_h[nxt][i*FDIM+f] = g_h[cur][i*FDIM+f] + 0.5f*acch;
    float4 vc = vcur[i*FDIM+f];
    g_v[nxt][i*FDIM+f] = make_float4(vc.x + 0.5f*av0, vc.y + 0.5f*av1, vc.z + 0.5f*av2, 0.f);
}

// ---------------- FUSED: update + con-mlp + msg-mlp(t+1), 8 nodes/block, 512 threads ----------------
// smem floats: B0[16384] | B1[16384] | B2[16384] | h_s[1024] | v_s[4096] | vn_s[1024] | hid_s[1024]
//            = 56320 floats = 225280 B
__global__ void __launch_bounds__(512) k_fused(
    const float* __restrict__ U,   const float* __restrict__ Vm,
    const float* __restrict__ uW1, const float* __restrict__ ub1,
    const float* __restrict__ uW2, const float* __restrict__ ub2,
    const float* __restrict__ cW1, const float* __restrict__ cb1,
    const float* __restrict__ cW2, const float* __restrict__ cb2,
    const float* __restrict__ mW1, const float* __restrict__ mb1,
    const float* __restrict__ mW2, const float* __restrict__ mb2,
    int buf, int do_msg)
{
    extern __shared__ float sm[];
    uint32_t smb = (uint32_t)__cvta_generic_to_shared(sm);
    uint32_t sB0 = smb, sB1 = smb + 16384*4, sB2 = smb + 32768*4;
    float*  B0    = sm;
    float*  B1    = sm + 16384;
    float*  B2    = sm + 32768;
    float*  h_s   = sm + 49152;
    float4* v_s   = (float4*)(sm + 50176);
    float*  vn_s  = sm + 54272;
    float*  hid_s = sm + 55296;
    int t = threadIdx.x;                // 512
    int g = t & 127, n0 = (t >> 7) * 2;
    int nb = blockIdx.x*8;
    float*  hb = g_h[buf];
    float4* vb = g_v[buf];
    const float4* uW2_4 = (const float4*)uW2;
    const float4* cW2_4 = (const float4*)cW2;
    const float4* mW2_4 = (const float4*)mW2;

    stage64(sB0, (const float4*)U,  t); CP_COMMIT();   // g0: B0=U
    stage64(sB1, (const float4*)Vm, t); CP_COMMIT();   // g1: B1=V
    stage64(sB2, (const float4*)uW1, t); CP_COMMIT();  // g2: B2=W1a
    for (int i = t; i < 8*FDIM; i += 512) {
        h_s[i] = hb[nb*FDIM + i];
        v_s[i] = vb[nb*FDIM + i];
    }

    // ---- P1: U,V GEMVs fused (B0,B1) ----
    CP_WAIT(1);
    __syncthreads();
    float au0[3] = {0.f,0.f,0.f}, au1[3] = {0.f,0.f,0.f};
    float av0[3] = {0.f,0.f,0.f}, av1[3] = {0.f,0.f,0.f};
    #pragma unroll 4
    for (int f = 0; f < FDIM; f++) {
        float uu = B0[f*FDIM+g];
        float vv = B1[f*FDIM+g];
        float4 x0 = v_s[n0*FDIM + f];
        float4 x1 = v_s[(n0+1)*FDIM + f];
        au0[0] += x0.x*uu; au0[1] += x0.y*uu; au0[2] += x0.z*uu;
        au1[0] += x1.x*uu; au1[1] += x1.y*uu; au1[2] += x1.z*uu;
        av0[0] += x0.x*vv; av0[1] += x0.y*vv; av0[2] += x0.z*vv;
        av1[0] += x1.x*vv; av1[1] += x1.y*vv; av1[2] += x1.z*vv;
    }
    float dot0 = au0[0]*av0[0] + au0[1]*av0[1] + au0[2]*av0[2];
    float dot1 = au1[0]*av1[0] + au1[1]*av1[1] + au1[2]*av1[2];
    vn_s[n0*FDIM + g]     = sqrtf(av0[0]*av0[0] + av0[1]*av0[1] + av0[2]*av0[2] + 1e-15f);
    vn_s[(n0+1)*FDIM + g] = sqrtf(av1[0]*av1[0] + av1[1]*av1[1] + av1[2]*av1[2] + 1e-15f);
    __syncthreads();
    stage64(sB0, ((const float4*)uW1) + 4096, t); CP_COMMIT();  // g3: B0=W1b
    stageW2(sB1, uW2_4, 0, t);                    CP_COMMIT();  // g4: B1=updW2c0

    // ---- P2: updL1 h part (B2=W1a) ----
    CP_WAIT(2);
    __syncthreads();
    float ac0 = ub1[g], ac1 = ac0;
    GEMV2(B2, h_s, ac0, ac1)
    __syncthreads();
    stageW2(sB2, uW2_4, 1, t); CP_COMMIT();                     // g5: B2=updW2c1

    // ---- P3: updL1 vn part (B0=W1b) -> hid ----
    CP_WAIT(2);
    __syncthreads();
    GEMV2(B0, vn_s, ac0, ac1)
    hid_s[n0*FDIM+g]     = silu(ac0);
    hid_s[(n0+1)*FDIM+g] = silu(ac1);
    __syncthreads();
    stageW2(sB0, uW2_4, 2, t); CP_COMMIT();                     // g6: B0=updW2c2

    // ---- P4: updW2c0 (B1) ----
    float A[3][2];
    CP_WAIT(2);
    __syncthreads();
    { float a0 = ub2[g], a1 = a0; GEMV2(B1, hid_s, a0, a1) A[0][0]=a0; A[0][1]=a1; }
    __syncthreads();
    stage64(sB1, (const float4*)cW1, t); CP_COMMIT();           // g7: B1=conW1

    // ---- P5: updW2c1 (B2) ----
    CP_WAIT(2);
    __syncthreads();
    { float a0 = ub2[128+g], a1 = a0; GEMV2(B2, hid_s, a0, a1) A[1][0]=a0; A[1][1]=a1; }
    __syncthreads();
    stageW2(sB2, cW2_4, 0, t); CP_COMMIT();                     // g8: B2=conW2c0

    // ---- P6: updW2c2 (B0) -> finish update, write new h/v, refresh h_s ----
    CP_WAIT(2);
    __syncthreads();
    { float a0 = ub2[256+g], a1 = a0; GEMV2(B0, hid_s, a0, a1) A[2][0]=a0; A[2][1]=a1; }
    float nh0, nh1;
    {
        float ds0 = dot0*A[1][0] + A[2][0];
        float ds1 = dot1*A[1][1] + A[2][1];
        nh0 = h_s[n0*FDIM+g]     + 0.5f*ds0;
        nh1 = h_s[(n0+1)*FDIM+g] + 0.5f*ds1;
        hb[(nb+n0  )*FDIM + g] = nh0;
        hb[(nb+n0+1)*FDIM + g] = nh1;
        float4 vo0 = v_s[n0*FDIM + g];
        float4 vo1 = v_s[(n0+1)*FDIM + g];
        vb[(nb+n0  )*FDIM + g] = make_float4(vo0.x + 0.5f*A[0][0]*au0[0],
                                             vo0.y + 0.5f*A[0][0]*au0[1],
                                             vo0.z + 0.5f*A[0][0]*au0[2], 0.f);
        vb[(nb+n0+1)*FDIM + g] = make_float4(vo1.x + 0.5f*A[0][1]*au1[0],
                                             vo1.y + 0.5f*A[0][1]*au1[1],
                                             vo1.z + 0.5f*A[0][1]*au1[2], 0.f);
        h_s[n0*FDIM+g]     = nh0;
        h_s[(n0+1)*FDIM+g] = nh1;
    }
    __syncthreads();
    stage64(sB0, (const float4*)mW1, t); CP_COMMIT();           // g9: B0=msgW1

    // ---- P7: conL1 (B1=conW1) on new h -> hid ----
    CP_WAIT(2);
    __syncthreads();
    { float a0 = cb1[g], a1 = a0; GEMV2(B1, h_s, a0, a1)
      hid_s[n0*FDIM+g] = silu(a0); hid_s[(n0+1)*FDIM+g] = silu(a1); }
    __syncthreads();
    stageW2(sB1, cW2_4, 1, t); CP_COMMIT();                     // g10: B1=conW2c1

    // ---- P8: conW2c0 (B2) ----
    CP_WAIT(2);
    __syncthreads();
    { float a0 = cb2[g], a1 = a0; GEMV2(B2, hid_s, a0, a1) A[0][0]=a0; A[0][1]=a1; }
    __syncthreads();
    stageW2(sB2, cW2_4, 2, t); CP_COMMIT();                     // g11: B2=conW2c2

    // ---- P9: conW2c1 (B1) ----
    CP_WAIT(2);
    __syncthreads();
    { float a0 = cb2[128+g], a1 = a0; GEMV2(B1, hid_s, a0, a1) A[1][0]=a0; A[1][1]=a1; }
    __syncthreads();
    stageW2(sB1, mW2_4, 0, t); CP_COMMIT();                     // g12: B1=msgW2c0

    // ---- P10: conW2c2 (B2) -> write g_phic ----
    CP_WAIT(2);
    __syncthreads();
    { float a0 = cb2[256+g], a1 = a0; GEMV2(B2, hid_s, a0, a1) A[2][0]=a0; A[2][1]=a1; }
    #pragma unroll
    for (int mm = 0; mm < 3; mm++) {
        int m = mm*128 + g;
        int oi = ((m % 3) << 7) + (m / 3);
        g_phic[(nb+n0  )*384 + oi] = A[mm][0];
        g_phic[(nb+n0+1)*384 + oi] = A[mm][1];
    }
    __syncthreads();
    stageW2(sB2, mW2_4, 1, t); CP_COMMIT();                     // g13: B2=msgW2c1

    // ---- P11: msgL1 (B0=msgW1) on new h -> hid ----
    CP_WAIT(2);
    __syncthreads();
    { float a0 = mb1[g], a1 = a0; GEMV2(B0, h_s, a0, a1)
      hid_s[n0*FDIM+g] = silu(a0); hid_s[(n0+1)*FDIM+g] = silu(a1); }
    __syncthreads();
    stageW2(sB0, mW2_4, 2, t); CP_COMMIT();                     // g14: B0=msgW2c2

    // ---- P12: msgW2c0 (B1) ----
    CP_WAIT(2);
    __syncthreads();
    { float a0 = mb2[g], a1 = a0; GEMV2(B1, hid_s, a0, a1) A[0][0]=a0; A[0][1]=a1; }

    // ---- P13: msgW2c1 (B2) ----
    CP_WAIT(1);
    __syncthreads();
    { float a0 = mb2[128+g], a1 = a0; GEMV2(B2, hid_s, a0, a1) A[1][0]=a0; A[1][1]=a1; }

    // ---- P14: msgW2c2 (B0) -> write g_phi4 ----
    CP_WAIT(0);
    __syncthreads();
    { float a0 = mb2[256+g], a1 = a0; GEMV2(B0, hid_s, a0, a1) A[2][0]=a0; A[2][1]=a1; }
    if (do_msg) {
        g_phi4[(nb+n0  )*FDIM + g] = make_float4(A[0][0], A[1][0], A[2][0], 0.f);
        g_phi4[(nb+n0+1)*FDIM + g] = make_float4(A[0][1], A[1][1], A[2][1], 0.f);
    }
}

// ---------------- contraction: fp16 table, 4 CG sites per block, 16-atom chunks ----------------
__global__ void __launch_bounds__(128) k_contract(int t, int buf,
    const float* __restrict__ bf,
    const float* __restrict__ xyz, const float* __restrict__ cgxyz,
    const float* __restrict__ assign, float* __restrict__ out)
{
    int f  = threadIdx.x;
    int b  = blockIdx.x >> 4;
    int cg0 = (blockIdx.x & 15) << 2;
    int a0 = blockIdx.y << 4;                 // 16 atoms per chunk, gridDim.y = 32
    const __half2* Tc = g_TconH + (size_t)t*PCON*384;
    const float4* vbuf = g_v[buf];
    float cx[4], cy[4], cz[4];
    #pragma unroll
    for (int c = 0; c < 4; c++) {
        int base = (b*NCGC + cg0 + c)*3;
        cx[c] = cgxyz[base]; cy[c] = cgxyz[base+1]; cz[c] = cgxyz[base+2];
    }
    float bf0 = bf[f*3+0], bf1 = bf[f*3+1], bf2 = bf[f*3+2];
    const float inv_step = (PCON-1)/DMAXC;
    float hacc[4], v0a[4], v1a[4], v2a[4];
    #pragma unroll
    for (int c = 0; c < 4; c++) { hacc[c]=0.f; v0a[c]=0.f; v1a[c]=0.f; v2a[c]=0.f; }
    for (int aa = 0; aa < 16; aa++) {
        int n = b*NNODES + a0 + aa;
        float px = xyz[3*n], py = xyz[3*n+1], pz = xyz[3*n+2];
        const float* pp = g_phic + n*384;
        float f0 = pp[f], f1 = pp[128+f], f2 = pp[256+f];
        float4 vp = vbuf[n*FDIM + f];
        const float* as = assign + n*NCGC + cg0;
        #pragma unroll
        for (int c = 0; c < 4; c++) {
            float rx = px - cx[c], ry = py - cy[c], rz = pz - cz[c];
            float d = sqrtf(rx*rx + ry*ry + rz*rz);
            float inv_d = 1.f/d;
            float s = as[c];
            float td = d*inv_step;
            int idx = (int)td;
            float fr;
            if (idx > PCON-2) { idx = PCON-2; fr = 1.f; } else fr = td - idx;
            const __half2* ba = Tc + idx*384;
            float2 q0 = __half22float2(ba[f]);
            float2 q1 = __half22float2(ba[128+f]);
            float2 q2 = __half22float2(ba[256+f]);
            float w0 = fmaf(fr, q0.y - q0.x, q0.x) + bf0;
            float w1 = fmaf(fr, q1.y - q1.x, q1.x) + bf1;
            float w2 = fmaf(fr, q2.y - q2.x, q2.x) + bf2;
            float x0 = w0*f0, x1 = w1*f1, x2 = w2*f2;
            hacc[c] += s*x1;
            v0a[c]  += s*(x2*(rx*inv_d) + x0*vp.x);
            v1a[c]  += s*(x2*(ry*inv_d) + x0*vp.y);
            v2a[c]  += s*(x2*(rz*inv_d) + x0*vp.z);
        }
    }
    #pragma unroll
    for (int c = 0; c < 4; c++) {
        int cc = b*NCGC + cg0 + c;
        atomicAdd(&out[cc*FDIM + f], hacc[c]);
        float* vout = out + BB*NCGC*FDIM + (cc*FDIM + f)*3;
        atomicAdd(vout+0, v0a[c]);
        atomicAdd(vout+1, v1a[c]);
        atomicAdd(vout+2, v2a[c]);
    }
}

// ---------------- host ----------------
#define MLP_SMEM (204800)
#define FUS_SMEM (225280)

extern "C" void kernel_launch(void* const* d_in, const int* in_sizes, int n_in,
                              void* d_out, int out_size)
{
    const float* h_in   = (const float*)d_in[0];
    const float* H_in   = (const float*)d_in[1];
    const float* xyz    = (const float*)d_in[2];
    const float* cgxyz  = (const float*)d_in[3];
    const float* assign = (const float*)d_in[4];
    const int*   nbr    = (const int*)  d_in[6];
    const float* msgW1  = (const float*)d_in[7];
    const float* msgb1  = (const float*)d_in[8];
    const float* msgW2  = (const float*)d_in[9];
    const float* msgb2  = (const float*)d_in[10];
    const float* We     = (const float*)d_in[11];
    const float* be     = (const float*)d_in[12];
    const float* updU   = (const float*)d_in[13];
    const float* updV   = (const float*)d_in[14];
    const float* updW1  = (const float*)d_in[15];
    const float* updb1  = (const float*)d_in[16];
    const float* updW2  = (const float*)d_in[17];
    const float* updb2  = (const float*)d_in[18];
    const float* conWf  = (const float*)d_in[19];
    const float* conbf  = (const float*)d_in[20];
    const float* conW1  = (const float*)d_in[21];
    const float* conb1  = (const float*)d_in[22];
    const float* conW2  = (const float*)d_in[23];
    const float* conb2  = (const float*)d_in[24];
    float* out = (float*)d_out;

    cudaFuncSetAttribute(k_mlp,   cudaFuncAttributeMaxDynamicSharedMemorySize, MLP_SMEM);
    cudaFuncSetAttribute(k_fused, cudaFuncAttributeMaxDynamicSharedMemorySize, FUS_SMEM);

    k_init_geom<<<ETOT/256, 256>>>(h_in, H_in, out, nbr, xyz);          // 1
    k_scan_fill<<<1, BN>>>();                                            // 2
    {
        dim3 gc(PCON/16, NCONVS);
        k_con_table<<<gc, 384>>>(conWf);                                 // 3
    }
    k_mlp<<<BN/8, 512, MLP_SMEM>>>(0, msgW1, msgb1, msgW2, msgb2, 0);    // 4 (profiled)
    {
        dim3 gm(PMSG, NCONVS);
        k_msg_table<<<gm, 128>>>(We, be);                                // 5
    }

    int cur = 0;
    for (int t = 0; t < NCONVS; t++) {
        int nxt = 1 - cur;
        k_edge<<<BN, 128>>>(t, cur, nxt);
        int tm = (t + 1 < NCONVS) ? (t + 1) : 0;   // msg weights for next iter (aliased on last)
        k_fused<<<BN/8, 512, FUS_SMEM>>>(
            updU + t*FDIM*FDIM, updV + t*FDIM*FDIM,
            updW1 + t*2*FDIM*FDIM, updb1 + t*FDIM,
            updW2 + t*FDIM*384,    updb2 + t*384,
            conW1 + t*FDIM*FDIM,   conb1 + t*FDIM,
            conW2 + t*FDIM*384,    conb2 + t*384,
            msgW1 + tm*FDIM*FDIM,  msgb1 + tm*FDIM,
            msgW2 + tm*FDIM*384,   msgb2 + tm*384,
            nxt, (t + 1 < NCONVS) ? 1 : 0);
        dim3 gk(BB*NCGC/4, 32);
        k_contract<<<gk, 128>>>(t, nxt, conbf + t*384, xyz, cgxyz, assign, out);
        cur = nxt;
    }
    (void)in_sizes; (void)n_in; (void)out_size;
}

// round 13
// speedup vs baseline: 1.0571x; 1.0571x over previous
#include <cuda_runtime.h>
#include <math.h>
#include <stdint.h>

#define BB      2
#define NNODES  512
#define NCGC    64
#define FDIM    128
#define NRBF    20
#define NCONVS  3
#define ETOT    32768
#define BN      (BB*NNODES)      // 1024
#define CUT     5.0f
#define PI_F    3.14159265358979323846f
#define PMSG    4096
#define PCON    1024
#define DMAXC   10.0f

// ---------------- persistent device scratch ----------------
__device__ float  g_h[2][BN*FDIM];
__device__ float4 g_v[2][BN*FDIM];
__device__ float4 g_phi4[BN*FDIM];            // (phi_e0, phi_e1, phi_e2, 0) per (node,f)
__device__ float  g_phic[BN*384];
__device__ float4 g_TmsgA[NCONVS*PMSG*FDIM];  // (w0[p], w0[p+1], w1[p], w1[p+1])
__device__ float2 g_TmsgB[NCONVS*PMSG*FDIM];  // (w2[p], w2[p+1])
__device__ float2 g_Tcon2[NCONVS*PCON*384];   // fp32 pair-packed (fp16 reverted: issue-bound, cvts hurt)
__device__ float  g_ed[ETOT];
__device__ float4 g_un[ETOT];
__device__ int    g_pi[ETOT], g_pj[ETOT];
__device__ int    g_ptrn[BN+1];
__device__ int    g_csr[ETOT];

__device__ __forceinline__ float silu(float x) { return x / (1.f + expf(-x)); }

#define CP_COMMIT() asm volatile("cp.async.commit_group;" ::: "memory")
#define CP_WAIT(n)  asm volatile("cp.async.wait_group %0;" :: "n"(n) : "memory")

// contiguous 64KB (4096 float4) global -> smem via cp.async, 512 threads
__device__ __forceinline__ void stage64(uint32_t sdst, const float4* __restrict__ src, int t)
{
    #pragma unroll
    for (int j = 0; j < 8; j++) {
        int i = t + j*512;
        asm volatile("cp.async.cg.shared.global [%0], [%1], 16;"
                     :: "r"(sdst + i*16), "l"(src + i) : "memory");
    }
}
// W2 chunk mm (128 rows x 128 cols out of 384-col rows) -> smem, 512 threads
__device__ __forceinline__ void stageW2(uint32_t sdst, const float4* __restrict__ W2_4, int mm, int t)
{
    #pragma unroll
    for (int j = 0; j < 8; j++) {
        int i = t + j*512;
        int k = i >> 5, c = i & 31;
        asm volatile("cp.async.cg.shared.global [%0], [%1], 16;"
                     :: "r"(sdst + i*16), "l"(W2_4 + k*96 + mm*32 + c) : "memory");
    }
}

// GEMV pair: out column g for nodes n0, n0+1, weights in BUF, input IN
#define GEMV2(BUF, IN, a0, a1) \
    _Pragma("unroll 8") \
    for (int k_ = 0; k_ < FDIM; k_ += 4) { \
        float4 h0_ = *(const float4*)&IN[n0*FDIM + k_]; \
        float4 h1_ = *(const float4*)&IN[(n0+1)*FDIM + k_]; \
        float w0_ = BUF[k_*FDIM+g], w1_ = BUF[(k_+1)*FDIM+g]; \
        float w2_ = BUF[(k_+2)*FDIM+g], w3_ = BUF[(k_+3)*FDIM+g]; \
        a0 += h0_.x*w0_ + h0_.y*w1_ + h0_.z*w2_ + h0_.w*w3_; \
        a1 += h1_.x*w0_ + h1_.y*w1_ + h1_.z*w2_ + h1_.w*w3_; \
    }

// ---------------- init (h/v/out) + edge geometry, fused ----------------
__global__ void k_init_geom(const float* __restrict__ h_in, const float* __restrict__ H_in,
                            float* __restrict__ out,
                            const int* __restrict__ nbr, const float* __restrict__ xyz)
{
    int idx = blockIdx.x*blockDim.x + threadIdx.x;   // 32768 threads exactly
    {
        int e = idx;
        int b  = nbr[3*e], ii = nbr[3*e+1], jj = nbr[3*e+2];
        int pi = b*NNODES + ii, pj = b*NNODES + jj;
        g_pi[e] = pi; g_pj[e] = pj;
        float rx = xyz[3*pi]   - xyz[3*pj];
        float ry = xyz[3*pi+1] - xyz[3*pj+1];
        float rz = xyz[3*pi+2] - xyz[3*pj+2];
        float d = sqrtf(rx*rx + ry*ry + rz*rz);
        g_ed[e] = d;
        float inv = 1.f/d;
        g_un[e] = make_float4(rx*inv, ry*inv, rz*inv, 0.f);
    }
    for (int i = idx; i < BN*FDIM; i += ETOT) {
        g_h[0][i] = h_in[i];
        g_v[0][i] = make_float4(0.f,0.f,0.f,0.f);
    }
    for (int i = idx; i < BB*NCGC*FDIM*4; i += ETOT)
        out[i] = (i < BB*NCGC*FDIM) ? H_in[i] : 0.f;
}

// ---------------- count + scan + CSR fill, one block, smem counters ----------------
__global__ void k_scan_fill()
{
    __shared__ int s_cnt[BN];
    __shared__ int s_scan[BN];
    __shared__ int s_fill[BN];
    int t = threadIdx.x;   // 1024
    s_cnt[t] = 0;
    __syncthreads();
    for (int e = t; e < ETOT; e += BN)
        if (g_ed[e] < CUT) atomicAdd(&s_cnt[g_pi[e]], 1);
    __syncthreads();
    s_scan[t] = s_cnt[t];
    __syncthreads();
    for (int off = 1; off < BN; off <<= 1) {
        int x = (t >= off) ? s_scan[t-off] : 0;
        __syncthreads();
        s_scan[t] += x;
        __syncthreads();
    }
    g_ptrn[t+1] = s_scan[t];
    if (t == 0) g_ptrn[0] = 0;
    s_cnt[t] = s_scan[t] - s_cnt[t];
    s_fill[t] = 0;
    __syncthreads();
    for (int e = t; e < ETOT; e += BN) {
        if (g_ed[e] < CUT) {
            int pi = g_pi[e];
            int pos = s_cnt[pi] + atomicAdd(&s_fill[pi], 1);
            g_csr[pos] = e;
        }
    }
}

// ---------------- message table (pair-packed float4/float2, f-indexed) ----------------
__global__ void k_msg_table(const float* __restrict__ We, const float* __restrict__ be)
{
    int p = blockIdx.x, t = blockIdx.y, f = threadIdx.x; // 128 threads
    const float step = CUT/(PMSG-1);
    float d0 = p*step;
    int p1i = (p+1 < PMSG) ? p+1 : PMSG-1;
    float d1 = p1i*step;
    float env0 = (d0 < CUT) ? 0.5f*(cosf(PI_F*d0/CUT) + 1.f) : 0.f;
    float env1 = (d1 < CUT) ? 0.5f*(cosf(PI_F*d1/CUT) + 1.f) : 0.f;
    __shared__ float rb[2][NRBF];
    if (f < 2*NRBF) {
        int which = f/NRBF, k = f%NRBF;
        float d = which ? d1 : d0;
        float dd = fmaxf(d, 1e-6f);
        rb[which][k] = sinf((k+1)*PI_F/CUT*dd)/dd;
    }
    __syncthreads();
    const float* Wt = We + t*NRBF*384;
    const float* bt = be + t*384;
    float b0 = bt[f], b1 = bt[128+f], b2 = bt[256+f];
    float w0p0=b0, w0p1=b0, w1p0=b1, w1p1=b1, w2p0=b2, w2p1=b2;
    #pragma unroll
    for (int k = 0; k < NRBF; k++) {
        float wa = Wt[k*384+f], wb = Wt[k*384+128+f], wc = Wt[k*384+256+f];
        float r0 = rb[0][k], r1 = rb[1][k];
        w0p0 += r0*wa; w0p1 += r1*wa;
        w1p0 += r0*wb; w1p1 += r1*wb;
        w2p0 += r0*wc; w2p1 += r1*wc;
    }
    int o = (t*PMSG+p)*FDIM + f;
    g_TmsgA[o] = make_float4(w0p0*env0, w0p1*env1, w1p0*env0, w1p1*env1);
    g_TmsgB[o] = make_float2(w2p0*env0, w2p1*env1);
}

// ---------------- contraction table (fp32 pair-packed, columns remapped to [e3][f]) ----------------
__global__ void k_con_table(const float* __restrict__ Wf)
{
    __shared__ float es[17][FDIM];
    int tid = threadIdx.x;              // 384 threads
    int p0  = blockIdx.x*16, t = blockIdx.y;
    const float step = DMAXC/(PCON-1);
    for (int i = tid; i < 17*FDIM; i += 384) {
        int pl = i / FDIM, k = i % FDIM;
        float d = (p0+pl)*step;
        float o = CUT*k/127.f;
        float x = d - o;
        es[pl][k] = expf(-x*x);
    }
    __syncthreads();
    int src = (tid & 127)*3 + (tid >> 7);
    float acc[17];
    #pragma unroll
    for (int p = 0; p < 17; p++) acc[p] = 0.f;
    const float* Wt = Wf + t*FDIM*384;
    for (int k = 0; k < FDIM; k++) {
        float w = Wt[k*384 + src];
        #pragma unroll
        for (int p = 0; p < 17; p++) acc[p] += es[p][k]*w;
    }
    #pragma unroll
    for (int p = 0; p < 16; p++)
        g_Tcon2[(t*PCON + p0 + p)*384 + tid] = make_float2(acc[p], acc[p+1]);
}

// ---------------- standalone MLP (msg t=0 only), R9 scalar form ----------------
// smem floats: wsW1[16384] | bufA[16384] | bufB[16384] | h_s[1024] | hid_s[1024] = 204800 B
__global__ void __launch_bounds__(512) k_mlp(int hsel,
                      const float* __restrict__ W1, const float* __restrict__ b1,
                      const float* __restrict__ W2, const float* __restrict__ b2, int dst_sel)
{
    extern __shared__ float sm[];
    uint32_t smb = (uint32_t)__cvta_generic_to_shared(sm);
    float* wsW1  = sm;
    float* bufA  = sm + 16384;
    float* bufB  = sm + 32768;
    float* h_s   = sm + 49152;
    float* hid_s = sm + 50176;
    int t = threadIdx.x;                // 512
    int nb = blockIdx.x*8;
    const float4* W2_4 = (const float4*)W2;

    stage64(smb,            (const float4*)W1, t); CP_COMMIT();
    stageW2(smb + 16384*4,  W2_4, 0, t);           CP_COMMIT();
    stageW2(smb + 32768*4,  W2_4, 1, t);           CP_COMMIT();
    const float* hb = g_h[hsel];
    for (int i = t; i < 8*FDIM; i += 512)
        h_s[i] = hb[nb*FDIM + i];

    CP_WAIT(2);
    __syncthreads();
    int g = t & 127, n0 = (t >> 7) * 2;
    {
        float a0 = b1[g], a1 = a0;
        GEMV2(wsW1, h_s, a0, a1)
        hid_s[n0*FDIM+g]     = silu(a0);
        hid_s[(n0+1)*FDIM+g] = silu(a1);
    }
    float A[3][2];
    CP_WAIT(1);
    __syncthreads();
    {
        float a0 = b2[g], a1 = a0;
        GEMV2(bufA, hid_s, a0, a1)
        A[0][0] = a0; A[0][1] = a1;
    }
    __syncthreads();
    stageW2(smb + 16384*4, W2_4, 2, t); CP_COMMIT();
    CP_WAIT(1);
    __syncthreads();
    {
        float a0 = b2[128+g], a1 = a0;
        GEMV2(bufB, hid_s, a0, a1)
        A[1][0] = a0; A[1][1] = a1;
    }
    CP_WAIT(0);
    __syncthreads();
    {
        float a0 = b2[256+g], a1 = a0;
        GEMV2(bufA, hid_s, a0, a1)
        A[2][0] = a0; A[2][1] = a1;
    }
    if (dst_sel == 0) {
        g_phi4[(nb+n0  )*FDIM + g] = make_float4(A[0][0], A[1][0], A[2][0], 0.f);
        g_phi4[(nb+n0+1)*FDIM + g] = make_float4(A[0][1], A[1][1], A[2][1], 0.f);
    } else {
        #pragma unroll
        for (int mm = 0; mm < 3; mm++) {
            int m = mm*128 + g;
            int oi = ((m % 3) << 7) + (m / 3);
            g_phic[(nb+n0  )*384 + oi] = A[mm][0];
            g_phic[(nb+n0+1)*384 + oi] = A[mm][1];
        }
    }
}

// ---------------- edge message pass: dual independent chains for 2x MLP ----------------
__global__ void __launch_bounds__(128) k_edge(int t, int cur, int nxt)
{
    int i = blockIdx.x, f = threadIdx.x;
    int e0 = g_ptrn[i], e1 = g_ptrn[i+1];
    const float4* TA = g_TmsgA + (size_t)t*PMSG*FDIM;
    const float2* TB = g_TmsgB + (size_t)t*PMSG*FDIM;
    const float4* vcur = g_v[cur];
    const float inv_step = (PMSG-1)/CUT;
    int cnt  = e1 - e0;
    int half = (cnt + 1) >> 1;
    int mid  = e0 + half;
    float acchA = 0.f, aA0 = 0.f, aA1 = 0.f, aA2 = 0.f;
    float acchB = 0.f, aB0 = 0.f, aB1 = 0.f, aB2 = 0.f;
    for (int m = 0; m < half; m++) {
        {   // chain A
            int e = g_csr[e0 + m];
            float d = g_ed[e];
            float u = d*inv_step;
            int idx = (int)u; if (idx > PMSG-2) idx = PMSG-2;
            float fr = u - idx;
            float4 Aq = TA[idx*FDIM + f];
            float2 Bq = TB[idx*FDIM + f];
            float w0 = fmaf(fr, Aq.y - Aq.x, Aq.x);
            float w1 = fmaf(fr, Aq.w - Aq.z, Aq.z);
            float w2 = fmaf(fr, Bq.y - Bq.x, Bq.x);
            int pj = g_pj[e];
            float4 ph = g_phi4[pj*FDIM + f];
            float i0 = ph.x*w0, i1 = ph.y*w1, i2 = ph.z*w2;
            float4 uq = g_un[e];
            float4 vj = vcur[pj*FDIM + f];
            acchA += i1;
            aA0   += i2*uq.x + i0*vj.x;
            aA1   += i2*uq.y + i0*vj.y;
            aA2   += i2*uq.z + i0*vj.z;
        }
        int q2 = mid + m;
        if (q2 < e1) {   // chain B (independent)
            int e = g_csr[q2];
            float d = g_ed[e];
            float u = d*inv_step;
            int idx = (int)u; if (idx > PMSG-2) idx = PMSG-2;
            float fr = u - idx;
            float4 Aq = TA[idx*FDIM + f];
            float2 Bq = TB[idx*FDIM + f];
            float w0 = fmaf(fr, Aq.y - Aq.x, Aq.x);
            float w1 = fmaf(fr, Aq.w - Aq.z, Aq.z);
            float w2 = fmaf(fr, Bq.y - Bq.x, Bq.x);
            int pj = g_pj[e];
            float4 ph = g_phi4[pj*FDIM + f];
            float i0 = ph.x*w0, i1 = ph.y*w1, i2 = ph.z*w2;
            float4 uq = g_un[e];
            float4 vj = vcur[pj*FDIM + f];
            acchB += i1;
            aB0   += i2*uq.x + i0*vj.x;
            aB1   += i2*uq.y + i0*vj.y;
            aB2   += i2*uq.z + i0*vj.z;
        }
    }
    float acch = acchA + acchB;
    float av0 = aA0 + aB0, av1 = aA1 + aB1, av2 = aA2 + aB2;
    g_h[nxt][i*FDIM+f] = g_h[cur][i*FDIM+f] + 0.5f*acch;
    float4 vc = vcur[i*FDIM+f];
    g_v[nxt][i*FDIM+f] = make_float4(vc.x + 0.5f*av0, vc.y + 0.5f*av1, vc.z + 0.5f*av2, 0.f);
}

// ---------------- FUSED: update + con-mlp + msg-mlp(t+1), 8 nodes/block, 512 threads ----------------
// smem floats: B0[16384] | B1[16384] | B2[16384] | h_s[1024] | v_s[4096] | vn_s[1024] | hid_s[1024]
//            = 56320 floats = 225280 B
__global__ void __launch_bounds__(512) k_fused(
    const float* __restrict__ U,   const float* __restrict__ Vm,
    const float* __restrict__ uW1, const float* __restrict__ ub1,
    const float* __restrict__ uW2, const float* __restrict__ ub2,
    const float* __restrict__ cW1, const float* __restrict__ cb1,
    const float* __restrict__ cW2, const float* __restrict__ cb2,
    const float* __restrict__ mW1, const float* __restrict__ mb1,
    const float* __restrict__ mW2, const float* __restrict__ mb2,
    int buf, int do_msg)
{
    extern __shared__ float sm[];
    uint32_t smb = (uint32_t)__cvta_generic_to_shared(sm);
    uint32_t sB0 = smb, sB1 = smb + 16384*4, sB2 = smb + 32768*4;
    float*  B0    = sm;
    float*  B1    = sm + 16384;
    float*  B2    = sm + 32768;
    float*  h_s   = sm + 49152;
    float4* v_s   = (float4*)(sm + 50176);
    float*  vn_s  = sm + 54272;
    float*  hid_s = sm + 55296;
    int t = threadIdx.x;                // 512
    int g = t & 127, n0 = (t >> 7) * 2;
    int nb = blockIdx.x*8;
    float*  hb = g_h[buf];
    float4* vb = g_v[buf];
    const float4* uW2_4 = (const float4*)uW2;
    const float4* cW2_4 = (const float4*)cW2;
    const float4* mW2_4 = (const float4*)mW2;

    stage64(sB0, (const float4*)U,  t); CP_COMMIT();   // g0: B0=U
    stage64(sB1, (const float4*)Vm, t); CP_COMMIT();   // g1: B1=V
    stage64(sB2, (const float4*)uW1, t); CP_COMMIT();  // g2: B2=W1a
    for (int i = t; i < 8*FDIM; i += 512) {
        h_s[i] = hb[nb*FDIM + i];
        v_s[i] = vb[nb*FDIM + i];
    }

    // ---- P1: U,V GEMVs fused (B0,B1) ----
    CP_WAIT(1);
    __syncthreads();
    float au0[3] = {0.f,0.f,0.f}, au1[3] = {0.f,0.f,0.f};
    float av0[3] = {0.f,0.f,0.f}, av1[3] = {0.f,0.f,0.f};
    #pragma unroll 4
    for (int f = 0; f < FDIM; f++) {
        float uu = B0[f*FDIM+g];
        float vv = B1[f*FDIM+g];
        float4 x0 = v_s[n0*FDIM + f];
        float4 x1 = v_s[(n0+1)*FDIM + f];
        au0[0] += x0.x*uu; au0[1] += x0.y*uu; au0[2] += x0.z*uu;
        au1[0] += x1.x*uu; au1[1] += x1.y*uu; au1[2] += x1.z*uu;
        av0[0] += x0.x*vv; av0[1] += x0.y*vv; av0[2] += x0.z*vv;
        av1[0] += x1.x*vv; av1[1] += x1.y*vv; av1[2] += x1.z*vv;
    }
    float dot0 = au0[0]*av0[0] + au0[1]*av0[1] + au0[2]*av0[2];
    float dot1 = au1[0]*av1[0] + au1[1]*av1[1] + au1[2]*av1[2];
    vn_s[n0*FDIM + g]     = sqrtf(av0[0]*av0[0] + av0[1]*av0[1] + av0[2]*av0[2] + 1e-15f);
    vn_s[(n0+1)*FDIM + g] = sqrtf(av1[0]*av1[0] + av1[1]*av1[1] + av1[2]*av1[2] + 1e-15f);
    __syncthreads();
    stage64(sB0, ((const float4*)uW1) + 4096, t); CP_COMMIT();  // g3: B0=W1b
    stageW2(sB1, uW2_4, 0, t);                    CP_COMMIT();  // g4: B1=updW2c0

    // ---- P2: updL1 h part (B2=W1a) ----
    CP_WAIT(2);
    __syncthreads();
    float ac0 = ub1[g], ac1 = ac0;
    GEMV2(B2, h_s, ac0, ac1)
    __syncthreads();
    stageW2(sB2, uW2_4, 1, t); CP_COMMIT();                     // g5: B2=updW2c1

    // ---- P3: updL1 vn part (B0=W1b) -> hid ----
    CP_WAIT(2);
    __syncthreads();
    GEMV2(B0, vn_s, ac0, ac1)
    hid_s[n0*FDIM+g]     = silu(ac0);
    hid_s[(n0+1)*FDIM+g] = silu(ac1);
    __syncthreads();
    stageW2(sB0, uW2_4, 2, t); CP_COMMIT();                     // g6: B0=updW2c2

    // ---- P4: updW2c0 (B1) ----
    float A[3][2];
    CP_WAIT(2);
    __syncthreads();
    { float a0 = ub2[g], a1 = a0; GEMV2(B1, hid_s, a0, a1) A[0][0]=a0; A[0][1]=a1; }
    __syncthreads();
    stage64(sB1, (const float4*)cW1, t); CP_COMMIT();           // g7: B1=conW1

    // ---- P5: updW2c1 (B2) ----
    CP_WAIT(2);
    __syncthreads();
    { float a0 = ub2[128+g], a1 = a0; GEMV2(B2, hid_s, a0, a1) A[1][0]=a0; A[1][1]=a1; }
    __syncthreads();
    stageW2(sB2, cW2_4, 0, t); CP_COMMIT();                     // g8: B2=conW2c0

    // ---- P6: updW2c2 (B0) -> finish update, write new h/v, refresh h_s ----
    CP_WAIT(2);
    __syncthreads();
    { float a0 = ub2[256+g], a1 = a0; GEMV2(B0, hid_s, a0, a1) A[2][0]=a0; A[2][1]=a1; }
    float nh0, nh1;
    {
        float ds0 = dot0*A[1][0] + A[2][0];
        float ds1 = dot1*A[1][1] + A[2][1];
        nh0 = h_s[n0*FDIM+g]     + 0.5f*ds0;
        nh1 = h_s[(n0+1)*FDIM+g] + 0.5f*ds1;
        hb[(nb+n0  )*FDIM + g] = nh0;
        hb[(nb+n0+1)*FDIM + g] = nh1;
        float4 vo0 = v_s[n0*FDIM + g];
        float4 vo1 = v_s[(n0+1)*FDIM + g];
        vb[(nb+n0  )*FDIM + g] = make_float4(vo0.x + 0.5f*A[0][0]*au0[0],
                                             vo0.y + 0.5f*A[0][0]*au0[1],
                                             vo0.z + 0.5f*A[0][0]*au0[2], 0.f);
        vb[(nb+n0+1)*FDIM + g] = make_float4(vo1.x + 0.5f*A[0][1]*au1[0],
                                             vo1.y + 0.5f*A[0][1]*au1[1],
                                             vo1.z + 0.5f*A[0][1]*au1[2], 0.f);
        h_s[n0*FDIM+g]     = nh0;
        h_s[(n0+1)*FDIM+g] = nh1;
    }
    __syncthreads();
    stage64(sB0, (const float4*)mW1, t); CP_COMMIT();           // g9: B0=msgW1

    // ---- P7: conL1 (B1=conW1) on new h -> hid ----
    CP_WAIT(2);
    __syncthreads();
    { float a0 = cb1[g], a1 = a0; GEMV2(B1, h_s, a0, a1)
      hid_s[n0*FDIM+g] = silu(a0); hid_s[(n0+1)*FDIM+g] = silu(a1); }
    __syncthreads();
    stageW2(sB1, cW2_4, 1, t); CP_COMMIT();                     // g10: B1=conW2c1

    // ---- P8: conW2c0 (B2) ----
    CP_WAIT(2);
    __syncthreads();
    { float a0 = cb2[g], a1 = a0; GEMV2(B2, hid_s, a0, a1) A[0][0]=a0; A[0][1]=a1; }
    __syncthreads();
    stageW2(sB2, cW2_4, 2, t); CP_COMMIT();                     // g11: B2=conW2c2

    // ---- P9: conW2c1 (B1) ----
    CP_WAIT(2);
    __syncthreads();
    { float a0 = cb2[128+g], a1 = a0; GEMV2(B1, hid_s, a0, a1) A[1][0]=a0; A[1][1]=a1; }
    __syncthreads();
    stageW2(sB1, mW2_4, 0, t); CP_COMMIT();                     // g12: B1=msgW2c0

    // ---- P10: conW2c2 (B2) -> write g_phic ----
    CP_WAIT(2);
    __syncthreads();
    { float a0 = cb2[256+g], a1 = a0; GEMV2(B2, hid_s, a0, a1) A[2][0]=a0; A[2][1]=a1; }
    #pragma unroll
    for (int mm = 0; mm < 3; mm++) {
        int m = mm*128 + g;
        int oi = ((m % 3) << 7) + (m / 3);
        g_phic[(nb+n0  )*384 + oi] = A[mm][0];
        g_phic[(nb+n0+1)*384 + oi] = A[mm][1];
    }
    __syncthreads();
    stageW2(sB2, mW2_4, 1, t); CP_COMMIT();                     // g13: B2=msgW2c1

    // ---- P11: msgL1 (B0=msgW1) on new h -> hid ----
    CP_WAIT(2);
    __syncthreads();
    { float a0 = mb1[g], a1 = a0; GEMV2(B0, h_s, a0, a1)
      hid_s[n0*FDIM+g] = silu(a0); hid_s[(n0+1)*FDIM+g] = silu(a1); }
    __syncthreads();
    stageW2(sB0, mW2_4, 2, t); CP_COMMIT();                     // g14: B0=msgW2c2

    // ---- P12: msgW2c0 (B1) ----
    CP_WAIT(2);
    __syncthreads();
    { float a0 = mb2[g], a1 = a0; GEMV2(B1, hid_s, a0, a1) A[0][0]=a0; A[0][1]=a1; }

    // ---- P13: msgW2c1 (B2) ----
    CP_WAIT(1);
    __syncthreads();
    { float a0 = mb2[128+g], a1 = a0; GEMV2(B2, hid_s, a0, a1) A[1][0]=a0; A[1][1]=a1; }

    // ---- P14: msgW2c2 (B0) -> write g_phi4 ----
    CP_WAIT(0);
    __syncthreads();
    { float a0 = mb2[256+g], a1 = a0; GEMV2(B0, hid_s, a0, a1) A[2][0]=a0; A[2][1]=a1; }
    if (do_msg) {
        g_phi4[(nb+n0  )*FDIM + g] = make_float4(A[0][0], A[1][0], A[2][0], 0.f);
        g_phi4[(nb+n0+1)*FDIM + g] = make_float4(A[0][1], A[1][1], A[2][1], 0.f);
    }
}

// ---------------- contraction: fp32 table, 4 CG sites per block, 16-atom chunks ----------------
__global__ void __launch_bounds__(128) k_contract(int t, int buf,
    const float* __restrict__ bf,
    const float* __restrict__ xyz, const float* __restrict__ cgxyz,
    const float* __restrict__ assign, float* __restrict__ out)
{
    int f  = threadIdx.x;
    int b  = blockIdx.x >> 4;
    int cg0 = (blockIdx.x & 15) << 2;
    int a0 = blockIdx.y << 4;                 // 16 atoms per chunk, gridDim.y = 32
    const float2* Tc = g_Tcon2 + (size_t)t*PCON*384;
    const float4* vbuf = g_v[buf];
    float cx[4], cy[4], cz[4];
    #pragma unroll
    for (int c = 0; c < 4; c++) {
        int base = (b*NCGC + cg0 + c)*3;
        cx[c] = cgxyz[base]; cy[c] = cgxyz[base+1]; cz[c] = cgxyz[base+2];
    }
    float bf0 = bf[f*3+0], bf1 = bf[f*3+1], bf2 = bf[f*3+2];
    const float inv_step = (PCON-1)/DMAXC;
    float hacc[4], v0a[4], v1a[4], v2a[4];
    #pragma unroll
    for (int c = 0; c < 4; c++) { hacc[c]=0.f; v0a[c]=0.f; v1a[c]=0.f; v2a[c]=0.f; }
    for (int aa = 0; aa < 16; aa++) {
        int n = b*NNODES + a0 + aa;
        float px = xyz[3*n], py = xyz[3*n+1], pz = xyz[3*n+2];
        const float* pp = g_phic + n*384;
        float f0 = pp[f], f1 = pp[128+f], f2 = pp[256+f];
        float4 vp = vbuf[n*FDIM + f];
        const float* as = assign + n*NCGC + cg0;
        #pragma unroll
        for (int c = 0; c < 4; c++) {
            float rx = px - cx[c], ry = py - cy[c], rz = pz - cz[c];
            float d = sqrtf(rx*rx + ry*ry + rz*rz);
            float inv_d = 1.f/d;
            float s = as[c];
            float td = d*inv_step;
            int idx = (int)td;
            float fr;
            if (idx > PCON-2) { idx = PCON-2; fr = 1.f; } else fr = td - idx;
            const float2* ba = Tc + idx*384;
            float2 q0 = ba[f], q1 = ba[128+f], q2 = ba[256+f];
            float w0 = fmaf(fr, q0.y - q0.x, q0.x) + bf0;
            float w1 = fmaf(fr, q1.y - q1.x, q1.x) + bf1;
            float w2 = fmaf(fr, q2.y - q2.x, q2.x) + bf2;
            float x0 = w0*f0, x1 = w1*f1, x2 = w2*f2;
            hacc[c] += s*x1;
            v0a[c]  += s*(x2*(rx*inv_d) + x0*vp.x);
            v1a[c]  += s*(x2*(ry*inv_d) + x0*vp.y);
            v2a[c]  += s*(x2*(rz*inv_d) + x0*vp.z);
        }
    }
    #pragma unroll
    for (int c = 0; c < 4; c++) {
        int cc = b*NCGC + cg0 + c;
        atomicAdd(&out[cc*FDIM + f], hacc[c]);
        float* vout = out + BB*NCGC*FDIM + (cc*FDIM + f)*3;
        atomicAdd(vout+0, v0a[c]);
        atomicAdd(vout+1, v1a[c]);
        atomicAdd(vout+2, v2a[c]);
    }
}

// ---------------- host ----------------
#define MLP_SMEM (204800)
#define FUS_SMEM (225280)

extern "C" void kernel_launch(void* const* d_in, const int* in_sizes, int n_in,
                              void* d_out, int out_size)
{
    const float* h_in   = (const float*)d_in[0];
    const float* H_in   = (const float*)d_in[1];
    const float* xyz    = (const float*)d_in[2];
    const float* cgxyz  = (const float*)d_in[3];
    const float* assign = (const float*)d_in[4];
    const int*   nbr    = (const int*)  d_in[6];
    const float* msgW1  = (const float*)d_in[7];
    const float* msgb1  = (const float*)d_in[8];
    const float* msgW2  = (const float*)d_in[9];
    const float* msgb2  = (const float*)d_in[10];
    const float* We     = (const float*)d_in[11];
    const float* be     = (const float*)d_in[12];
    const float* updU   = (const float*)d_in[13];
    const float* updV   = (const float*)d_in[14];
    const float* updW1  = (const float*)d_in[15];
    const float* updb1  = (const float*)d_in[16];
    const float* updW2  = (const float*)d_in[17];
    const float* updb2  = (const float*)d_in[18];
    const float* conWf  = (const float*)d_in[19];
    const float* conbf  = (const float*)d_in[20];
    const float* conW1  = (const float*)d_in[21];
    const float* conb1  = (const float*)d_in[22];
    const float* conW2  = (const float*)d_in[23];
    const float* conb2  = (const float*)d_in[24];
    float* out = (float*)d_out;

    cudaFuncSetAttribute(k_mlp,   cudaFuncAttributeMaxDynamicSharedMemorySize, MLP_SMEM);
    cudaFuncSetAttribute(k_fused, cudaFuncAttributeMaxDynamicSharedMemorySize, FUS_SMEM);

    k_init_geom<<<ETOT/256, 256>>>(h_in, H_in, out, nbr, xyz);          // 1
    k_scan_fill<<<1, BN>>>();                                            // 2
    {
        dim3 gc(PCON/16, NCONVS);
        k_con_table<<<gc, 384>>>(conWf);                                 // 3
    }
    k_mlp<<<BN/8, 512, MLP_SMEM>>>(0, msgW1, msgb1, msgW2, msgb2, 0);    // 4 (profiled)
    {
        dim3 gm(PMSG, NCONVS);
        k_msg_table<<<gm, 128>>>(We, be);                                // 5
    }

    int cur = 0;
    for (int t = 0; t < NCONVS; t++) {
        int nxt = 1 - cur;
        k_edge<<<BN, 128>>>(t, cur, nxt);
        int tm = (t + 1 < NCONVS) ? (t + 1) : 0;   // msg weights for next iter (aliased on last)
        k_fused<<<BN/8, 512, FUS_SMEM>>>(
            updU + t*FDIM*FDIM, updV + t*FDIM*FDIM,
            updW1 + t*2*FDIM*FDIM, updb1 + t*FDIM,
            updW2 + t*FDIM*384,    updb2 + t*384,
            conW1 + t*FDIM*FDIM,   conb1 + t*FDIM,
            conW2 + t*FDIM*384,    conb2 + t*384,
            msgW1 + tm*FDIM*FDIM,  msgb1 + tm*FDIM,
            msgW2 + tm*FDIM*384,   msgb2 + tm*384,
            nxt, (t + 1 < NCONVS) ? 1 : 0);
        dim3 gk(BB*NCGC/4, 32);
        k_contract<<<gk, 128>>>(t, nxt, conbf + t*384, xyz, cgxyz, assign, out);
        cur = nxt;
    }
    (void)in_sizes; (void)n_in; (void)out_size;
}

// round 14
// speedup vs baseline: 1.2061x; 1.1410x over previous
#include <cuda_runtime.h>
#include <math.h>
#include <stdint.h>

#define BB      2
#define NNODES  512
#define NCGC    64
#define FDIM    128
#define NRBF    20
#define NCONVS  3
#define ETOT    32768
#define BN      (BB*NNODES)      // 1024
#define CUT     5.0f
#define PI_F    3.14159265358979323846f
#define PMSG    4096
#define PCON    1024
#define DMAXC   10.0f

// ---------------- persistent device scratch ----------------
__device__ float  g_h[2][BN*FDIM];
__device__ float4 g_v[2][BN*FDIM];
__device__ float4 g_phi4[BN*FDIM];
__device__ float  g_phic[BN*384];
__device__ float4 g_TmsgA[NCONVS*PMSG*FDIM];
__device__ float2 g_TmsgB[NCONVS*PMSG*FDIM];
__device__ float2 g_Tcon2[NCONVS*PCON*384];
__device__ float  g_ed[ETOT];
__device__ float4 g_un[ETOT];
__device__ int    g_pi[ETOT], g_pj[ETOT];
__device__ int    g_ptrn[BN+1];
__device__ int    g_csr[ETOT];

__device__ __forceinline__ float silu(float x) { return x / (1.f + expf(-x)); }

#define CP_COMMIT() asm volatile("cp.async.commit_group;" ::: "memory")
#define CP_WAIT(n)  asm volatile("cp.async.wait_group %0;" :: "n"(n) : "memory")

__device__ __forceinline__ void stage64(uint32_t sdst, const float4* __restrict__ src, int t)
{
    #pragma unroll
    for (int j = 0; j < 8; j++) {
        int i = t + j*512;
        asm volatile("cp.async.cg.shared.global [%0], [%1], 16;"
                     :: "r"(sdst + i*16), "l"(src + i) : "memory");
    }
}
__device__ __forceinline__ void stageW2(uint32_t sdst, const float4* __restrict__ W2_4, int mm, int t)
{
    #pragma unroll
    for (int j = 0; j < 8; j++) {
        int i = t + j*512;
        int k = i >> 5, c = i & 31;
        asm volatile("cp.async.cg.shared.global [%0], [%1], 16;"
                     :: "r"(sdst + i*16), "l"(W2_4 + k*96 + mm*32 + c) : "memory");
    }
}

// single GEMV pair: out column g for nodes n0,n0+1
#define GEMV2(BUF, IN, a0, a1) \
    _Pragma("unroll 8") \
    for (int k_ = 0; k_ < FDIM; k_ += 4) { \
        float4 h0_ = *(const float4*)&IN[n0*FDIM + k_]; \
        float4 h1_ = *(const float4*)&IN[(n0+1)*FDIM + k_]; \
        float w0_ = BUF[k_*FDIM+g], w1_ = BUF[(k_+1)*FDIM+g]; \
        float w2_ = BUF[(k_+2)*FDIM+g], w3_ = BUF[(k_+3)*FDIM+g]; \
        a0 += h0_.x*w0_ + h0_.y*w1_ + h0_.z*w2_ + h0_.w*w3_; \
        a1 += h1_.x*w0_ + h1_.y*w1_ + h1_.z*w2_ + h1_.w*w3_; \
    }

// paired GEMVs from two resident buffers (4 independent chains)
#define GEMV2x2(BUFa, BUFb, IN, a0, a1, c0, c1) \
    _Pragma("unroll 4") \
    for (int k_ = 0; k_ < FDIM; k_ += 4) { \
        float4 h0_ = *(const float4*)&IN[n0*FDIM + k_]; \
        float4 h1_ = *(const float4*)&IN[(n0+1)*FDIM + k_]; \
        float p0_ = BUFa[k_*FDIM+g], p1_ = BUFa[(k_+1)*FDIM+g]; \
        float p2_ = BUFa[(k_+2)*FDIM+g], p3_ = BUFa[(k_+3)*FDIM+g]; \
        float q0_ = BUFb[k_*FDIM+g], q1_ = BUFb[(k_+1)*FDIM+g]; \
        float q2_ = BUFb[(k_+2)*FDIM+g], q3_ = BUFb[(k_+3)*FDIM+g]; \
        a0 += h0_.x*p0_ + h0_.y*p1_ + h0_.z*p2_ + h0_.w*p3_; \
        a1 += h1_.x*p0_ + h1_.y*p1_ + h1_.z*p2_ + h1_.w*p3_; \
        c0 += h0_.x*q0_ + h0_.y*q1_ + h0_.z*q2_ + h0_.w*q3_; \
        c1 += h1_.x*q0_ + h1_.y*q1_ + h1_.z*q2_ + h1_.w*q3_; \
    }

// ---------------- init (h/v/out) + edge geometry, fused ----------------
__global__ void k_init_geom(const float* __restrict__ h_in, const float* __restrict__ H_in,
                            float* __restrict__ out,
                            const int* __restrict__ nbr, const float* __restrict__ xyz)
{
    int idx = blockIdx.x*blockDim.x + threadIdx.x;
    {
        int e = idx;
        int b  = nbr[3*e], ii = nbr[3*e+1], jj = nbr[3*e+2];
        int pi = b*NNODES + ii, pj = b*NNODES + jj;
        g_pi[e] = pi; g_pj[e] = pj;
        float rx = xyz[3*pi]   - xyz[3*pj];
        float ry = xyz[3*pi+1] - xyz[3*pj+1];
        float rz = xyz[3*pi+2] - xyz[3*pj+2];
        float d = sqrtf(rx*rx + ry*ry + rz*rz);
        g_ed[e] = d;
        float inv = 1.f/d;
        g_un[e] = make_float4(rx*inv, ry*inv, rz*inv, 0.f);
    }
    for (int i = idx; i < BN*FDIM; i += ETOT) {
        g_h[0][i] = h_in[i];
        g_v[0][i] = make_float4(0.f,0.f,0.f,0.f);
    }
    for (int i = idx; i < BB*NCGC*FDIM*4; i += ETOT)
        out[i] = (i < BB*NCGC*FDIM) ? H_in[i] : 0.f;
}

// ---------------- count + scan + CSR fill ----------------
__global__ void k_scan_fill()
{
    __shared__ int s_cnt[BN];
    __shared__ int s_scan[BN];
    __shared__ int s_fill[BN];
    int t = threadIdx.x;
    s_cnt[t] = 0;
    __syncthreads();
    for (int e = t; e < ETOT; e += BN)
        if (g_ed[e] < CUT) atomicAdd(&s_cnt[g_pi[e]], 1);
    __syncthreads();
    s_scan[t] = s_cnt[t];
    __syncthreads();
    for (int off = 1; off < BN; off <<= 1) {
        int x = (t >= off) ? s_scan[t-off] : 0;
        __syncthreads();
        s_scan[t] += x;
        __syncthreads();
    }
    g_ptrn[t+1] = s_scan[t];
    if (t == 0) g_ptrn[0] = 0;
    s_cnt[t] = s_scan[t] - s_cnt[t];
    s_fill[t] = 0;
    __syncthreads();
    for (int e = t; e < ETOT; e += BN) {
        if (g_ed[e] < CUT) {
            int pi = g_pi[e];
            int pos = s_cnt[pi] + atomicAdd(&s_fill[pi], 1);
            g_csr[pos] = e;
        }
    }
}

// ---------------- message table ----------------
__global__ void k_msg_table(const float* __restrict__ We, const float* __restrict__ be)
{
    int p = blockIdx.x, t = blockIdx.y, f = threadIdx.x;
    const float step = CUT/(PMSG-1);
    float d0 = p*step;
    int p1i = (p+1 < PMSG) ? p+1 : PMSG-1;
    float d1 = p1i*step;
    float env0 = (d0 < CUT) ? 0.5f*(cosf(PI_F*d0/CUT) + 1.f) : 0.f;
    float env1 = (d1 < CUT) ? 0.5f*(cosf(PI_F*d1/CUT) + 1.f) : 0.f;
    __shared__ float rb[2][NRBF];
    if (f < 2*NRBF) {
        int which = f/NRBF, k = f%NRBF;
        float d = which ? d1 : d0;
        float dd = fmaxf(d, 1e-6f);
        rb[which][k] = sinf((k+1)*PI_F/CUT*dd)/dd;
    }
    __syncthreads();
    const float* Wt = We + t*NRBF*384;
    const float* bt = be + t*384;
    float b0 = bt[f], b1 = bt[128+f], b2 = bt[256+f];
    float w0p0=b0, w0p1=b0, w1p0=b1, w1p1=b1, w2p0=b2, w2p1=b2;
    #pragma unroll
    for (int k = 0; k < NRBF; k++) {
        float wa = Wt[k*384+f], wb = Wt[k*384+128+f], wc = Wt[k*384+256+f];
        float r0 = rb[0][k], r1 = rb[1][k];
        w0p0 += r0*wa; w0p1 += r1*wa;
        w1p0 += r0*wb; w1p1 += r1*wb;
        w2p0 += r0*wc; w2p1 += r1*wc;
    }
    int o = (t*PMSG+p)*FDIM + f;
    g_TmsgA[o] = make_float4(w0p0*env0, w0p1*env1, w1p0*env0, w1p1*env1);
    g_TmsgB[o] = make_float2(w2p0*env0, w2p1*env1);
}

// ---------------- contraction table ----------------
__global__ void k_con_table(const float* __restrict__ Wf)
{
    __shared__ float es[17][FDIM];
    int tid = threadIdx.x;
    int p0  = blockIdx.x*16, t = blockIdx.y;
    const float step = DMAXC/(PCON-1);
    for (int i = tid; i < 17*FDIM; i += 384) {
        int pl = i / FDIM, k = i % FDIM;
        float d = (p0+pl)*step;
        float o = CUT*k/127.f;
        float x = d - o;
        es[pl][k] = expf(-x*x);
    }
    __syncthreads();
    int src = (tid & 127)*3 + (tid >> 7);
    float acc[17];
    #pragma unroll
    for (int p = 0; p < 17; p++) acc[p] = 0.f;
    const float* Wt = Wf + t*FDIM*384;
    for (int k = 0; k < FDIM; k++) {
        float w = Wt[k*384 + src];
        #pragma unroll
        for (int p = 0; p < 17; p++) acc[p] += es[p][k]*w;
    }
    #pragma unroll
    for (int p = 0; p < 16; p++)
        g_Tcon2[(t*PCON + p0 + p)*384 + tid] = make_float2(acc[p], acc[p+1]);
}

// ---------------- standalone MLP (msg t=0), 3 phases with paired W2 c0+c1 ----------------
// smem floats: wsW1[16384] | bufA[16384] | bufB[16384] | h_s[1024] | hid_s[1024] = 204800 B
__global__ void __launch_bounds__(512) k_mlp(int hsel,
                      const float* __restrict__ W1, const float* __restrict__ b1,
                      const float* __restrict__ W2, const float* __restrict__ b2, int dst_sel)
{
    extern __shared__ float sm[];
    uint32_t smb = (uint32_t)__cvta_generic_to_shared(sm);
    float* wsW1  = sm;
    float* bufA  = sm + 16384;
    float* bufB  = sm + 32768;
    float* h_s   = sm + 49152;
    float* hid_s = sm + 50176;
    int t = threadIdx.x;
    int nb = blockIdx.x*8;
    const float4* W2_4 = (const float4*)W2;

    stage64(smb,            (const float4*)W1, t); CP_COMMIT();
    stageW2(smb + 16384*4,  W2_4, 0, t);           CP_COMMIT();
    stageW2(smb + 32768*4,  W2_4, 1, t);           CP_COMMIT();
    const float* hb = g_h[hsel];
    for (int i = t; i < 8*FDIM; i += 512)
        h_s[i] = hb[nb*FDIM + i];

    CP_WAIT(2);
    __syncthreads();
    int g = t & 127, n0 = (t >> 7) * 2;
    {
        float a0 = b1[g], a1 = a0;
        GEMV2(wsW1, h_s, a0, a1)
        hid_s[n0*FDIM+g]     = silu(a0);
        hid_s[(n0+1)*FDIM+g] = silu(a1);
    }
    float A[3][2];
    CP_WAIT(0);
    __syncthreads();
    {   // paired chunk0 (bufA) + chunk1 (bufB)
        float a0 = b2[g], a1 = a0;
        float c0 = b2[128+g], c1 = c0;
        GEMV2x2(bufA, bufB, hid_s, a0, a1, c0, c1)
        A[0][0]=a0; A[0][1]=a1; A[1][0]=c0; A[1][1]=c1;
    }
    __syncthreads();
    stageW2(smb + 16384*4, W2_4, 2, t); CP_COMMIT();
    CP_WAIT(0);
    __syncthreads();
    {
        float a0 = b2[256+g], a1 = a0;
        GEMV2(bufA, hid_s, a0, a1)
        A[2][0] = a0; A[2][1] = a1;
    }
    if (dst_sel == 0) {
        g_phi4[(nb+n0  )*FDIM + g] = make_float4(A[0][0], A[1][0], A[2][0], 0.f);
        g_phi4[(nb+n0+1)*FDIM + g] = make_float4(A[0][1], A[1][1], A[2][1], 0.f);
    } else {
        #pragma unroll
        for (int mm = 0; mm < 3; mm++) {
            int m = mm*128 + g;
            int oi = ((m % 3) << 7) + (m / 3);
            g_phic[(nb+n0  )*384 + oi] = A[mm][0];
            g_phic[(nb+n0+1)*384 + oi] = A[mm][1];
        }
    }
}

// ---------------- merged: edge(t) blocks [0,BN) + contract(t-1) blocks [BN,2BN) ----------------
__global__ void __launch_bounds__(128) k_edge_con(int te, int cur, int nxt,
    int tc, const float* __restrict__ bf,
    const float* __restrict__ xyz, const float* __restrict__ cgxyz,
    const float* __restrict__ assign, float* __restrict__ out)
{
    if (blockIdx.x < BN) {
        // ---- edge part ----
        int i = blockIdx.x, f = threadIdx.x;
        int e0 = g_ptrn[i], e1 = g_ptrn[i+1];
        const float4* TA = g_TmsgA + (size_t)te*PMSG*FDIM;
        const float2* TB = g_TmsgB + (size_t)te*PMSG*FDIM;
        const float4* vcur = g_v[cur];
        const float inv_step = (PMSG-1)/CUT;
        float acch = 0.f, av0 = 0.f, av1 = 0.f, av2 = 0.f;
        for (int q = e0; q < e1; q++) {
            int e = g_csr[q];
            float d = g_ed[e];
            float u = d*inv_step;
            int idx = (int)u; if (idx > PMSG-2) idx = PMSG-2;
            float fr = u - idx;
            float4 Aq = TA[idx*FDIM + f];
            float2 Bq = TB[idx*FDIM + f];
            float w0 = fmaf(fr, Aq.y - Aq.x, Aq.x);
            float w1 = fmaf(fr, Aq.w - Aq.z, Aq.z);
            float w2 = fmaf(fr, Bq.y - Bq.x, Bq.x);
            int pj = g_pj[e];
            float4 ph = g_phi4[pj*FDIM + f];
            float i0 = ph.x*w0, i1 = ph.y*w1, i2 = ph.z*w2;
            float4 uq = g_un[e];
            float4 vj = vcur[pj*FDIM + f];
            acch += i1;
            av0  += i2*uq.x + i0*vj.x;
            av1  += i2*uq.y + i0*vj.y;
            av2  += i2*uq.z + i0*vj.z;
        }
        g_h[nxt][i*FDIM+f] = g_h[cur][i*FDIM+f] + 0.5f*acch;
        float4 vc = vcur[i*FDIM+f];
        g_v[nxt][i*FDIM+f] = make_float4(vc.x + 0.5f*av0, vc.y + 0.5f*av1, vc.z + 0.5f*av2, 0.f);
    } else {
        // ---- contract part (iteration tc, reads buffer `cur`) ----
        int q  = blockIdx.x - BN;
        int ib = q & 31;
        int b  = ib >> 4;
        int cg0 = (ib & 15) << 2;
        int a0 = (q >> 5) << 4;
        int f  = threadIdx.x;
        const float2* Tc = g_Tcon2 + (size_t)tc*PCON*384;
        const float4* vbuf = g_v[cur];
        float cx[4], cy[4], cz[4];
        #pragma unroll
        for (int c = 0; c < 4; c++) {
            int base = (b*NCGC + cg0 + c)*3;
            cx[c] = cgxyz[base]; cy[c] = cgxyz[base+1]; cz[c] = cgxyz[base+2];
        }
        float bf0 = bf[f*3+0], bf1 = bf[f*3+1], bf2 = bf[f*3+2];
        const float inv_step = (PCON-1)/DMAXC;
        float hacc[4], v0a[4], v1a[4], v2a[4];
        #pragma unroll
        for (int c = 0; c < 4; c++) { hacc[c]=0.f; v0a[c]=0.f; v1a[c]=0.f; v2a[c]=0.f; }
        for (int aa = 0; aa < 16; aa++) {
            int n = b*NNODES + a0 + aa;
            float px = xyz[3*n], py = xyz[3*n+1], pz = xyz[3*n+2];
            const float* pp = g_phic + n*384;
            float f0 = pp[f], f1 = pp[128+f], f2 = pp[256+f];
            float4 vp = vbuf[n*FDIM + f];
            const float* as = assign + n*NCGC + cg0;
            #pragma unroll
            for (int c = 0; c < 4; c++) {
                float rx = px - cx[c], ry = py - cy[c], rz = pz - cz[c];
                float d = sqrtf(rx*rx + ry*ry + rz*rz);
                float inv_d = 1.f/d;
                float s = as[c];
                float td = d*inv_step;
                int idx = (int)td;
                float fr;
                if (idx > PCON-2) { idx = PCON-2; fr = 1.f; } else fr = td - idx;
                const float2* ba = Tc + idx*384;
                float2 q0 = ba[f], q1 = ba[128+f], q2 = ba[256+f];
                float w0 = fmaf(fr, q0.y - q0.x, q0.x) + bf0;
                float w1 = fmaf(fr, q1.y - q1.x, q1.x) + bf1;
                float w2 = fmaf(fr, q2.y - q2.x, q2.x) + bf2;
                float x0 = w0*f0, x1 = w1*f1, x2 = w2*f2;
                hacc[c] += s*x1;
                v0a[c]  += s*(x2*(rx*inv_d) + x0*vp.x);
                v1a[c]  += s*(x2*(ry*inv_d) + x0*vp.y);
                v2a[c]  += s*(x2*(rz*inv_d) + x0*vp.z);
            }
        }
        #pragma unroll
        for (int c = 0; c < 4; c++) {
            int cc = b*NCGC + cg0 + c;
            atomicAdd(&out[cc*FDIM + f], hacc[c]);
            float* vout = out + BB*NCGC*FDIM + (cc*FDIM + f)*3;
            atomicAdd(vout+0, v0a[c]);
            atomicAdd(vout+1, v1a[c]);
            atomicAdd(vout+2, v2a[c]);
        }
    }
}

// ---------------- final standalone contract ----------------
__global__ void __launch_bounds__(128) k_contract(int t, int buf,
    const float* __restrict__ bf,
    const float* __restrict__ xyz, const float* __restrict__ cgxyz,
    const float* __restrict__ assign, float* __restrict__ out)
{
    int f  = threadIdx.x;
    int b  = blockIdx.x >> 4;
    int cg0 = (blockIdx.x & 15) << 2;
    int a0 = blockIdx.y << 4;
    const float2* Tc = g_Tcon2 + (size_t)t*PCON*384;
    const float4* vbuf = g_v[buf];
    float cx[4], cy[4], cz[4];
    #pragma unroll
    for (int c = 0; c < 4; c++) {
        int base = (b*NCGC + cg0 + c)*3;
        cx[c] = cgxyz[base]; cy[c] = cgxyz[base+1]; cz[c] = cgxyz[base+2];
    }
    float bf0 = bf[f*3+0], bf1 = bf[f*3+1], bf2 = bf[f*3+2];
    const float inv_step = (PCON-1)/DMAXC;
    float hacc[4], v0a[4], v1a[4], v2a[4];
    #pragma unroll
    for (int c = 0; c < 4; c++) { hacc[c]=0.f; v0a[c]=0.f; v1a[c]=0.f; v2a[c]=0.f; }
    for (int aa = 0; aa < 16; aa++) {
        int n = b*NNODES + a0 + aa;
        float px = xyz[3*n], py = xyz[3*n+1], pz = xyz[3*n+2];
        const float* pp = g_phic + n*384;
        float f0 = pp[f], f1 = pp[128+f], f2 = pp[256+f];
        float4 vp = vbuf[n*FDIM + f];
        const float* as = assign + n*NCGC + cg0;
        #pragma unroll
        for (int c = 0; c < 4; c++) {
            float rx = px - cx[c], ry = py - cy[c], rz = pz - cz[c];
            float d = sqrtf(rx*rx + ry*ry + rz*rz);
            float inv_d = 1.f/d;
            float s = as[c];
            float td = d*inv_step;
            int idx = (int)td;
            float fr;
            if (idx > PCON-2) { idx = PCON-2; fr = 1.f; } else fr = td - idx;
            const float2* ba = Tc + idx*384;
            float2 q0 = ba[f], q1 = ba[128+f], q2 = ba[256+f];
            float w0 = fmaf(fr, q0.y - q0.x, q0.x) + bf0;
            float w1 = fmaf(fr, q1.y - q1.x, q1.x) + bf1;
            float w2 = fmaf(fr, q2.y - q2.x, q2.x) + bf2;
            float x0 = w0*f0, x1 = w1*f1, x2 = w2*f2;
            hacc[c] += s*x1;
            v0a[c]  += s*(x2*(rx*inv_d) + x0*vp.x);
            v1a[c]  += s*(x2*(ry*inv_d) + x0*vp.y);
            v2a[c]  += s*(x2*(rz*inv_d) + x0*vp.z);
        }
    }
    #pragma unroll
    for (int c = 0; c < 4; c++) {
        int cc = b*NCGC + cg0 + c;
        atomicAdd(&out[cc*FDIM + f], hacc[c]);
        float* vout = out + BB*NCGC*FDIM + (cc*FDIM + f)*3;
        atomicAdd(vout+0, v0a[c]);
        atomicAdd(vout+1, v1a[c]);
        atomicAdd(vout+2, v2a[c]);
    }
}

// ---------------- FUSED node kernel: 11 phases (paired W2 chunks), 15 staged groups ----------------
// smem floats: B0[16384] | B1[16384] | B2[16384] | h_s[1024] | v_s[4096] | vn_s[1024] | hid_s[1024]
__global__ void __launch_bounds__(512) k_fused(
    const float* __restrict__ U,   const float* __restrict__ Vm,
    const float* __restrict__ uW1, const float* __restrict__ ub1,
    const float* __restrict__ uW2, const float* __restrict__ ub2,
    const float* __restrict__ cW1, const float* __restrict__ cb1,
    const float* __restrict__ cW2, const float* __restrict__ cb2,
    const float* __restrict__ mW1, const float* __restrict__ mb1,
    const float* __restrict__ mW2, const float* __restrict__ mb2,
    int buf, int do_msg)
{
    extern __shared__ float sm[];
    uint32_t smb = (uint32_t)__cvta_generic_to_shared(sm);
    uint32_t sB0 = smb, sB1 = smb + 16384*4, sB2 = smb + 32768*4;
    float*  B0    = sm;
    float*  B1    = sm + 16384;
    float*  B2    = sm + 32768;
    float*  h_s   = sm + 49152;
    float4* v_s   = (float4*)(sm + 50176);
    float*  vn_s  = sm + 54272;
    float*  hid_s = sm + 55296;
    int t = threadIdx.x;
    int g = t & 127, n0 = (t >> 7) * 2;
    int nb = blockIdx.x*8;
    float*  hb = g_h[buf];
    float4* vb = g_v[buf];
    const float4* uW2_4 = (const float4*)uW2;
    const float4* cW2_4 = (const float4*)cW2;
    const float4* mW2_4 = (const float4*)mW2;

    stage64(sB0, (const float4*)U,  t); CP_COMMIT();   // g0: B0=U
    stage64(sB1, (const float4*)Vm, t); CP_COMMIT();   // g1: B1=V
    stage64(sB2, (const float4*)uW1, t); CP_COMMIT();  // g2: B2=uW1a
    for (int i = t; i < 8*FDIM; i += 512) {
        h_s[i] = hb[nb*FDIM + i];
        v_s[i] = vb[nb*FDIM + i];
    }

    // ---- P1: U,V GEMVs fused (B0,B1) ----
    CP_WAIT(1);
    __syncthreads();
    float au0[3] = {0.f,0.f,0.f}, au1[3] = {0.f,0.f,0.f};
    float av0[3] = {0.f,0.f,0.f}, av1[3] = {0.f,0.f,0.f};
    #pragma unroll 4
    for (int f = 0; f < FDIM; f++) {
        float uu = B0[f*FDIM+g];
        float vv = B1[f*FDIM+g];
        float4 x0 = v_s[n0*FDIM + f];
        float4 x1 = v_s[(n0+1)*FDIM + f];
        au0[0] += x0.x*uu; au0[1] += x0.y*uu; au0[2] += x0.z*uu;
        au1[0] += x1.x*uu; au1[1] += x1.y*uu; au1[2] += x1.z*uu;
        av0[0] += x0.x*vv; av0[1] += x0.y*vv; av0[2] += x0.z*vv;
        av1[0] += x1.x*vv; av1[1] += x1.y*vv; av1[2] += x1.z*vv;
    }
    float dot0 = au0[0]*av0[0] + au0[1]*av0[1] + au0[2]*av0[2];
    float dot1 = au1[0]*av1[0] + au1[1]*av1[1] + au1[2]*av1[2];
    vn_s[n0*FDIM + g]     = sqrtf(av0[0]*av0[0] + av0[1]*av0[1] + av0[2]*av0[2] + 1e-15f);
    vn_s[(n0+1)*FDIM + g] = sqrtf(av1[0]*av1[0] + av1[1]*av1[1] + av1[2]*av1[2] + 1e-15f);
    __syncthreads();
    stage64(sB0, ((const float4*)uW1) + 4096, t); CP_COMMIT();  // g3: B0=uW1b
    stageW2(sB1, uW2_4, 0, t);                    CP_COMMIT();  // g4: B1=uW2c0

    // ---- P2: updL1 h part (B2=uW1a) ----      [out: g3,g4]
    CP_WAIT(2);
    __syncthreads();
    float ac0 = ub1[g], ac1 = ac0;
    GEMV2(B2, h_s, ac0, ac1)
    __syncthreads();
    stageW2(sB2, uW2_4, 1, t); CP_COMMIT();                     // g5: B2=uW2c1

    // ---- P3: updL1 vn part (B0=uW1b) -> hid ----  [out: g4,g5]
    CP_WAIT(2);
    __syncthreads();
    GEMV2(B0, vn_s, ac0, ac1)
    hid_s[n0*FDIM+g]     = silu(ac0);
    hid_s[(n0+1)*FDIM+g] = silu(ac1);
    __syncthreads();
    stageW2(sB0, uW2_4, 2, t); CP_COMMIT();                     // g6: B0=uW2c2

    // ---- P4: uW2 c0+c1 paired (B1,B2) ----   [out: g6]
    float A[3][2];
    CP_WAIT(1);
    __syncthreads();
    {
        float a0 = ub2[g], a1 = a0;
        float c0 = ub2[128+g], c1 = c0;
        GEMV2x2(B1, B2, hid_s, a0, a1, c0, c1)
        A[0][0]=a0; A[0][1]=a1; A[1][0]=c0; A[1][1]=c1;
    }
    __syncthreads();
    stage64(sB1, (const float4*)cW1, t); CP_COMMIT();           // g7: B1=cW1
    stageW2(sB2, cW2_4, 0, t);           CP_COMMIT();           // g8: B2=cW2c0

    // ---- P5: uW2c2 (B0) -> finish update, write new h/v ----  [out: g7,g8]
    CP_WAIT(2);
    __syncthreads();
    { float a0 = ub2[256+g], a1 = a0; GEMV2(B0, hid_s, a0, a1) A[2][0]=a0; A[2][1]=a1; }
    {
        float ds0 = dot0*A[1][0] + A[2][0];
        float ds1 = dot1*A[1][1] + A[2][1];
        float nh0 = h_s[n0*FDIM+g]     + 0.5f*ds0;
        float nh1 = h_s[(n0+1)*FDIM+g] + 0.5f*ds1;
        hb[(nb+n0  )*FDIM + g] = nh0;
        hb[(nb+n0+1)*FDIM + g] = nh1;
        float4 vo0 = v_s[n0*FDIM + g];
        float4 vo1 = v_s[(n0+1)*FDIM + g];
        vb[(nb+n0  )*FDIM + g] = make_float4(vo0.x + 0.5f*A[0][0]*au0[0],
                                             vo0.y + 0.5f*A[0][0]*au0[1],
                                             vo0.z + 0.5f*A[0][0]*au0[2], 0.f);
        vb[(nb+n0+1)*FDIM + g] = make_float4(vo1.x + 0.5f*A[0][1]*au1[0],
                                             vo1.y + 0.5f*A[0][1]*au1[1],
                                             vo1.z + 0.5f*A[0][1]*au1[2], 0.f);
        h_s[n0*FDIM+g]     = nh0;
        h_s[(n0+1)*FDIM+g] = nh1;
    }
    __syncthreads();
    stageW2(sB0, cW2_4, 1, t); CP_COMMIT();                     // g9: B0=cW2c1

    // ---- P6: conL1 (B1=cW1) -> hid ----       [out: g8,g9]
    CP_WAIT(2);
    __syncthreads();
    { float a0 = cb1[g], a1 = a0; GEMV2(B1, h_s, a0, a1)
      hid_s[n0*FDIM+g] = silu(a0); hid_s[(n0+1)*FDIM+g] = silu(a1); }
    __syncthreads();
    stageW2(sB1, cW2_4, 2, t); CP_COMMIT();                     // g10: B1=cW2c2

    // ---- P7: cW2 c0+c1 paired (B2,B0) ----    [out: g10]
    CP_WAIT(1);
    __syncthreads();
    {
        float a0 = cb2[g], a1 = a0;
        float c0 = cb2[128+g], c1 = c0;
        GEMV2x2(B2, B0, hid_s, a0, a1, c0, c1)
        A[0][0]=a0; A[0][1]=a1; A[1][0]=c0; A[1][1]=c1;
    }
    __syncthreads();
    stage64(sB2, (const float4*)mW1, t); CP_COMMIT();           // g11: B2=mW1
    stageW2(sB0, mW2_4, 0, t);           CP_COMMIT();           // g12: B0=mW2c0

    // ---- P8: cW2c2 (B1) -> write g_phic ----  [out: g11,g12]
    CP_WAIT(2);
    __syncthreads();
    { float a0 = cb2[256+g], a1 = a0; GEMV2(B1, hid_s, a0, a1) A[2][0]=a0; A[2][1]=a1; }
    #pragma unroll
    for (int mm = 0; mm < 3; mm++) {
        int m = mm*128 + g;
        int oi = ((m % 3) << 7) + (m / 3);
        g_phic[(nb+n0  )*384 + oi] = A[mm][0];
        g_phic[(nb+n0+1)*384 + oi] = A[mm][1];
    }
    __syncthreads();
    stageW2(sB1, mW2_4, 1, t); CP_COMMIT();                     // g13: B1=mW2c1

    // ---- P9: msgL1 (B2=mW1) -> hid ----       [out: g12,g13]
    CP_WAIT(2);
    __syncthreads();
    { float a0 = mb1[g], a1 = a0; GEMV2(B2, h_s, a0, a1)
      hid_s[n0*FDIM+g] = silu(a0); hid_s[(n0+1)*FDIM+g] = silu(a1); }
    __syncthreads();
    stageW2(sB2, mW2_4, 2, t); CP_COMMIT();                     // g14: B2=mW2c2

    // ---- P10: mW2 c0+c1 paired (B0,B1) ----   [out: g14]
    CP_WAIT(1);
    __syncthreads();
    {
        float a0 = mb2[g], a1 = a0;
        float c0 = mb2[128+g], c1 = c0;
        GEMV2x2(B0, B1, hid_s, a0, a1, c0, c1)
        A[0][0]=a0; A[0][1]=a1; A[1][0]=c0; A[1][1]=c1;
    }

    // ---- P11: mW2c2 (B2) -> write g_phi4 ----
    CP_WAAIT_PLACEHOLDER:;
    CP_WAIT(0);
    __syncthreads();
    { float a0 = mb2[256+g], a1 = a0; GEMV2(B2, hid_s, a0, a1) A[2][0]=a0; A[2][1]=a1; }
    if (do_msg) {
        g_phi4[(nb+n0  )*FDIM + g] = make_float4(A[0][0], A[1][0], A[2][0], 0.f);
        g_phi4[(nb+n0+1)*FDIM + g] = make_float4(A[0][1], A[1][1], A[2][1], 0.f);
    }
}

// ---------------- host ----------------
#define MLP_SMEM (204800)
#define FUS_SMEM (225280)

extern "C" void kernel_launch(void* const* d_in, const int* in_sizes, int n_in,
                              void* d_out, int out_size)
{
    const float* h_in   = (const float*)d_in[0];
    const float* H_in   = (const float*)d_in[1];
    const float* xyz    = (const float*)d_in[2];
    const float* cgxyz  = (const float*)d_in[3];
    const float* assign = (const float*)d_in[4];
    const int*   nbr    = (const int*)  d_in[6];
    const float* msgW1  = (const float*)d_in[7];
    const float* msgb1  = (const float*)d_in[8];
    const float* msgW2  = (const float*)d_in[9];
    const float* msgb2  = (const float*)d_in[10];
    const float* We     = (const float*)d_in[11];
    const float* be     = (const float*)d_in[12];
    const float* updU   = (const float*)d_in[13];
    const float* updV   = (const float*)d_in[14];
    const float* updW1  = (const float*)d_in[15];
    const float* updb1  = (const float*)d_in[16];
    const float* updW2  = (const float*)d_in[17];
    const float* updb2  = (const float*)d_in[18];
    const float* conWf  = (const float*)d_in[19];
    const float* conbf  = (const float*)d_in[20];
    const float* conW1  = (const float*)d_in[21];
    const float* conb1  = (const float*)d_in[22];
    const float* conW2  = (const float*)d_in[23];
    const float* conb2  = (const float*)d_in[24];
    float* out = (float*)d_out;

    cudaFuncSetAttribute(k_mlp,   cudaFuncAttributeMaxDynamicSharedMemorySize, MLP_SMEM);
    cudaFuncSetAttribute(k_fused, cudaFuncAttributeMaxDynamicSharedMemorySize, FUS_SMEM);

    k_init_geom<<<ETOT/256, 256>>>(h_in, H_in, out, nbr, xyz);          // 1
    k_scan_fill<<<1, BN>>>();                                            // 2
    {
        dim3 gc(PCON/16, NCONVS);
        k_con_table<<<gc, 384>>>(conWf);                                 // 3
    }
    k_mlp<<<BN/8, 512, MLP_SMEM>>>(0, msgW1, msgb1, msgW2, msgb2, 0);    // 4 (profiled)
    {
        dim3 gm(PMSG, NCONVS);
        k_msg_table<<<gm, 128>>>(We, be);                                // 5
    }

    int cur = 0;
    for (int t = 0; t < NCONVS; t++) {
        int nxt = 1 - cur;
        if (t == 0) {
            k_edge_con<<<BN, 128>>>(t, cur, nxt, 0, conbf, xyz, cgxyz, assign, out);
        } else {
            // edge(t) + contract(t-1); contract reads buffer `cur` (written by fused(t-1))
            k_edge_con<<<2*BN, 128>>>(t, cur, nxt, t-1, conbf + (t-1)*384,
                                      xyz, cgxyz, assign, out);
        }
        int tm = (t + 1 < NCONVS) ? (t + 1) : 0;
        k_fused<<<BN/8, 512, FUS_SMEM>>>(
            updU + t*FDIM*FDIM, updV + t*FDIM*FDIM,
            updW1 + t*2*FDIM*FDIM, updb1 + t*FDIM,
            updW2 + t*FDIM*384,    updb2 + t*384,
            conW1 + t*FDIM*FDIM,   conb1 + t*FDIM,
            conW2 + t*FDIM*384,    conb2 + t*384,
            msgW1 + tm*FDIM*FDIM,  msgb1 + tm*FDIM,
            msgW2 + tm*FDIM*384,   msgb2 + tm*384,
            nxt, (t + 1 < NCONVS) ? 1 : 0);
        cur = nxt;
    }
    // final contract for t = NCONVS-1 (reads buffer `cur` written by last fused)
    {
        dim3 gk(BB*NCGC/4, 32);
        k_contract<<<gk, 128>>>(NCONVS-1, cur, conbf + (NCONVS-1)*384,
                                xyz, cgxyz, assign, out);
    }
    (void)in_sizes; (void)n_in; (void)out_size;
}

// round 15
// speedup vs baseline: 1.2659x; 1.0496x over previous
#include <cuda_runtime.h>
#include <math.h>
#include <stdint.h>

#define BB      2
#define NNODES  512
#define NCGC    64
#define FDIM    128
#define NRBF    20
#define NCONVS  3
#define ETOT    32768
#define BN      (BB*NNODES)      // 1024
#define CUT     5.0f
#define PI_F    3.14159265358979323846f
#define PMSG    4096
#define PCON    1024
#define DMAXC   10.0f

// ---------------- persistent device scratch ----------------
__device__ float  g_h[2][BN*FDIM];
__device__ float4 g_v[2][BN*FDIM];
__device__ float4 g_phi4[BN*FDIM];
__device__ float  g_phic[BN*384];
__device__ float4 g_TmsgA[NCONVS*PMSG*FDIM];
__device__ float2 g_TmsgB[NCONVS*PMSG*FDIM];
__device__ float2 g_Tcon2[NCONVS*PCON*384];
__device__ float  g_ed[ETOT];
__device__ float4 g_un[ETOT];
__device__ int    g_pi[ETOT], g_pj[ETOT];
__device__ int    g_cnt[BN], g_fill[BN], g_ptrn[BN+1];
__device__ int    g_csr[ETOT];

__device__ __forceinline__ float silu(float x) { return x / (1.f + expf(-x)); }

#define CP_COMMIT() asm volatile("cp.async.commit_group;" ::: "memory")
#define CP_WAIT(n)  asm volatile("cp.async.wait_group %0;" :: "n"(n) : "memory")

__device__ __forceinline__ void stage64(uint32_t sdst, const float4* __restrict__ src, int t)
{
    #pragma unroll
    for (int j = 0; j < 8; j++) {
        int i = t + j*512;
        asm volatile("cp.async.cg.shared.global [%0], [%1], 16;"
                     :: "r"(sdst + i*16), "l"(src + i) : "memory");
    }
}
__device__ __forceinline__ void stageW2(uint32_t sdst, const float4* __restrict__ W2_4, int mm, int t)
{
    #pragma unroll
    for (int j = 0; j < 8; j++) {
        int i = t + j*512;
        int k = i >> 5, c = i & 31;
        asm volatile("cp.async.cg.shared.global [%0], [%1], 16;"
                     :: "r"(sdst + i*16), "l"(W2_4 + k*96 + mm*32 + c) : "memory");
    }
}

#define GEMV2(BUF, IN, a0, a1) \
    _Pragma("unroll 8") \
    for (int k_ = 0; k_ < FDIM; k_ += 4) { \
        float4 h0_ = *(const float4*)&IN[n0*FDIM + k_]; \
        float4 h1_ = *(const float4*)&IN[(n0+1)*FDIM + k_]; \
        float w0_ = BUF[k_*FDIM+g], w1_ = BUF[(k_+1)*FDIM+g]; \
        float w2_ = BUF[(k_+2)*FDIM+g], w3_ = BUF[(k_+3)*FDIM+g]; \
        a0 += h0_.x*w0_ + h0_.y*w1_ + h0_.z*w2_ + h0_.w*w3_; \
        a1 += h1_.x*w0_ + h1_.y*w1_ + h1_.z*w2_ + h1_.w*w3_; \
    }

#define GEMV2x2(BUFa, BUFb, IN, a0, a1, c0, c1) \
    _Pragma("unroll 4") \
    for (int k_ = 0; k_ < FDIM; k_ += 4) { \
        float4 h0_ = *(const float4*)&IN[n0*FDIM + k_]; \
        float4 h1_ = *(const float4*)&IN[(n0+1)*FDIM + k_]; \
        float p0_ = BUFa[k_*FDIM+g], p1_ = BUFa[(k_+1)*FDIM+g]; \
        float p2_ = BUFa[(k_+2)*FDIM+g], p3_ = BUFa[(k_+3)*FDIM+g]; \
        float q0_ = BUFb[k_*FDIM+g], q1_ = BUFb[(k_+1)*FDIM+g]; \
        float q2_ = BUFb[(k_+2)*FDIM+g], q3_ = BUFb[(k_+3)*FDIM+g]; \
        a0 += h0_.x*p0_ + h0_.y*p1_ + h0_.z*p2_ + h0_.w*p3_; \
        a1 += h1_.x*p0_ + h1_.y*p1_ + h1_.z*p2_ + h1_.w*p3_; \
        c0 += h0_.x*q0_ + h0_.y*q1_ + h0_.z*q2_ + h0_.w*q3_; \
        c1 += h1_.x*q0_ + h1_.y*q1_ + h1_.z*q2_ + h1_.w*q3_; \
    }

// ---------------- init (h/v/out, zero counters) + edge geometry ----------------
__global__ void k_init_geom(const float* __restrict__ h_in, const float* __restrict__ H_in,
                            float* __restrict__ out,
                            const int* __restrict__ nbr, const float* __restrict__ xyz)
{
    int idx = blockIdx.x*blockDim.x + threadIdx.x;
    {
        int e = idx;
        int b  = nbr[3*e], ii = nbr[3*e+1], jj = nbr[3*e+2];
        int pi = b*NNODES + ii, pj = b*NNODES + jj;
        g_pi[e] = pi; g_pj[e] = pj;
        float rx = xyz[3*pi]   - xyz[3*pj];
        float ry = xyz[3*pi+1] - xyz[3*pj+1];
        float rz = xyz[3*pi+2] - xyz[3*pj+2];
        float d = sqrtf(rx*rx + ry*ry + rz*rz);
        g_ed[e] = d;
        float inv = 1.f/d;
        g_un[e] = make_float4(rx*inv, ry*inv, rz*inv, 0.f);
    }
    for (int i = idx; i < BN*FDIM; i += ETOT) {
        g_h[0][i] = h_in[i];
        g_v[0][i] = make_float4(0.f,0.f,0.f,0.f);
    }
    for (int i = idx; i < BB*NCGC*FDIM*4; i += ETOT)
        out[i] = (i < BB*NCGC*FDIM) ? H_in[i] : 0.f;
    if (idx < BN) { g_cnt[idx] = 0; g_fill[idx] = 0; }
}

// ---------------- full-chip degree count ----------------
__global__ void k_count()
{
    int e = blockIdx.x*256 + threadIdx.x;
    if (e >= ETOT) return;
    if (g_ed[e] < CUT) atomicAdd(&g_cnt[g_pi[e]], 1);
}

// ---------------- 1-block exclusive scan of 1024 degrees ----------------
__global__ void k_scan()
{
    __shared__ int s[BN];
    int t = threadIdx.x;   // 1024
    s[t] = g_cnt[t];
    __syncthreads();
    for (int off = 1; off < BN; off <<= 1) {
        int x = (t >= off) ? s[t-off] : 0;
        __syncthreads();
        s[t] += x;
        __syncthreads();
    }
    g_ptrn[t+1] = s[t];
    if (t == 0) g_ptrn[0] = 0;
}

// ---------------- full-chip CSR fill ----------------
__global__ void k_fill()
{
    int e = blockIdx.x*256 + threadIdx.x;
    if (e >= ETOT) return;
    if (g_ed[e] >= CUT) return;
    int pi = g_pi[e];
    int pos = g_ptrn[pi] + atomicAdd(&g_fill[pi], 1);
    g_csr[pos] = e;
}

// ---------------- message table ----------------
__global__ void k_msg_table(const float* __restrict__ We, const float* __restrict__ be)
{
    int p = blockIdx.x, t = blockIdx.y, f = threadIdx.x;
    const float step = CUT/(PMSG-1);
    float d0 = p*step;
    int p1i = (p+1 < PMSG) ? p+1 : PMSG-1;
    float d1 = p1i*step;
    float env0 = (d0 < CUT) ? 0.5f*(cosf(PI_F*d0/CUT) + 1.f) : 0.f;
    float env1 = (d1 < CUT) ? 0.5f*(cosf(PI_F*d1/CUT) + 1.f) : 0.f;
    __shared__ float rb[2][NRBF];
    if (f < 2*NRBF) {
        int which = f/NRBF, k = f%NRBF;
        float d = which ? d1 : d0;
        float dd = fmaxf(d, 1e-6f);
        rb[which][k] = sinf((k+1)*PI_F/CUT*dd)/dd;
    }
    __syncthreads();
    const float* Wt = We + t*NRBF*384;
    const float* bt = be + t*384;
    float b0 = bt[f], b1 = bt[128+f], b2 = bt[256+f];
    float w0p0=b0, w0p1=b0, w1p0=b1, w1p1=b1, w2p0=b2, w2p1=b2;
    #pragma unroll
    for (int k = 0; k < NRBF; k++) {
        float wa = Wt[k*384+f], wb = Wt[k*384+128+f], wc = Wt[k*384+256+f];
        float r0 = rb[0][k], r1 = rb[1][k];
        w0p0 += r0*wa; w0p1 += r1*wa;
        w1p0 += r0*wb; w1p1 += r1*wb;
        w2p0 += r0*wc; w2p1 += r1*wc;
    }
    int o = (t*PMSG+p)*FDIM + f;
    g_TmsgA[o] = make_float4(w0p0*env0, w0p1*env1, w1p0*env0, w1p1*env1);
    g_TmsgB[o] = make_float2(w2p0*env0, w2p1*env1);
}

// ---------------- contraction table ----------------
__global__ void k_con_table(const float* __restrict__ Wf)
{
    __shared__ float es[17][FDIM];
    int tid = threadIdx.x;
    int p0  = blockIdx.x*16, t = blockIdx.y;
    const float step = DMAXC/(PCON-1);
    for (int i = tid; i < 17*FDIM; i += 384) {
        int pl = i / FDIM, k = i % FDIM;
        float d = (p0+pl)*step;
        float o = CUT*k/127.f;
        float x = d - o;
        es[pl][k] = expf(-x*x);
    }
    __syncthreads();
    int src = (tid & 127)*3 + (tid >> 7);
    float acc[17];
    #pragma unroll
    for (int p = 0; p < 17; p++) acc[p] = 0.f;
    const float* Wt = Wf + t*FDIM*384;
    for (int k = 0; k < FDIM; k++) {
        float w = Wt[k*384 + src];
        #pragma unroll
        for (int p = 0; p < 17; p++) acc[p] += es[p][k]*w;
    }
    #pragma unroll
    for (int p = 0; p < 16; p++)
        g_Tcon2[(t*PCON + p0 + p)*384 + tid] = make_float2(acc[p], acc[p+1]);
}

// ---------------- standalone MLP (msg t=0), paired W2 c0+c1 ----------------
__global__ void __launch_bounds__(512) k_mlp(int hsel,
                      const float* __restrict__ W1, const float* __restrict__ b1,
                      const float* __restrict__ W2, const float* __restrict__ b2, int dst_sel)
{
    extern __shared__ float sm[];
    uint32_t smb = (uint32_t)__cvta_generic_to_shared(sm);
    float* wsW1  = sm;
    float* bufA  = sm + 16384;
    float* bufB  = sm + 32768;
    float* h_s   = sm + 49152;
    float* hid_s = sm + 50176;
    int t = threadIdx.x;
    int nb = blockIdx.x*8;
    const float4* W2_4 = (const float4*)W2;

    stage64(smb,            (const float4*)W1, t); CP_COMMIT();
    stageW2(smb + 16384*4,  W2_4, 0, t);           CP_COMMIT();
    stageW2(smb + 32768*4,  W2_4, 1, t);           CP_COMMIT();
    const float* hb = g_h[hsel];
    for (int i = t; i < 8*FDIM; i += 512)
        h_s[i] = hb[nb*FDIM + i];

    CP_WAIT(2);
    __syncthreads();
    int g = t & 127, n0 = (t >> 7) * 2;
    {
        float a0 = b1[g], a1 = a0;
        GEMV2(wsW1, h_s, a0, a1)
        hid_s[n0*FDIM+g]     = silu(a0);
        hid_s[(n0+1)*FDIM+g] = silu(a1);
    }
    float A[3][2];
    CP_WAIT(0);
    __syncthreads();
    {
        float a0 = b2[g], a1 = a0;
        float c0 = b2[128+g], c1 = c0;
        GEMV2x2(bufA, bufB, hid_s, a0, a1, c0, c1)
        A[0][0]=a0; A[0][1]=a1; A[1][0]=c0; A[1][1]=c1;
    }
    __syncthreads();
    stageW2(smb + 16384*4, W2_4, 2, t); CP_COMMIT();
    CP_WAIT(0);
    __syncthreads();
    {
        float a0 = b2[256+g], a1 = a0;
        GEMV2(bufA, hid_s, a0, a1)
        A[2][0] = a0; A[2][1] = a1;
    }
    if (dst_sel == 0) {
        g_phi4[(nb+n0  )*FDIM + g] = make_float4(A[0][0], A[1][0], A[2][0], 0.f);
        g_phi4[(nb+n0+1)*FDIM + g] = make_float4(A[0][1], A[1][1], A[2][1], 0.f);
    } else {
        #pragma unroll
        for (int mm = 0; mm < 3; mm++) {
            int m = mm*128 + g;
            int oi = ((m % 3) << 7) + (m / 3);
            g_phic[(nb+n0  )*384 + oi] = A[mm][0];
            g_phic[(nb+n0+1)*384 + oi] = A[mm][1];
        }
    }
}

// ---------------- merged: edge(t) blocks [0,BN) + contract(t-1) blocks [BN,2BN) ----------------
__global__ void __launch_bounds__(128) k_edge_con(int te, int cur, int nxt,
    int tc, const float* __restrict__ bf,
    const float* __restrict__ xyz, const float* __restrict__ cgxyz,
    const float* __restrict__ assign, float* __restrict__ out)
{
    if (blockIdx.x < BN) {
        int i = blockIdx.x, f = threadIdx.x;
        int e0 = g_ptrn[i], e1 = g_ptrn[i+1];
        const float4* TA = g_TmsgA + (size_t)te*PMSG*FDIM;
        const float2* TB = g_TmsgB + (size_t)te*PMSG*FDIM;
        const float4* vcur = g_v[cur];
        const float inv_step = (PMSG-1)/CUT;
        float acch = 0.f, av0 = 0.f, av1 = 0.f, av2 = 0.f;
        for (int q = e0; q < e1; q++) {
            int e = g_csr[q];
            float d = g_ed[e];
            float u = d*inv_step;
            int idx = (int)u; if (idx > PMSG-2) idx = PMSG-2;
            float fr = u - idx;
            float4 Aq = TA[idx*FDIM + f];
            float2 Bq = TB[idx*FDIM + f];
            float w0 = fmaf(fr, Aq.y - Aq.x, Aq.x);
            float w1 = fmaf(fr, Aq.w - Aq.z, Aq.z);
            float w2 = fmaf(fr, Bq.y - Bq.x, Bq.x);
            int pj = g_pj[e];
            float4 ph = g_phi4[pj*FDIM + f];
            float i0 = ph.x*w0, i1 = ph.y*w1, i2 = ph.z*w2;
            float4 uq = g_un[e];
            float4 vj = vcur[pj*FDIM + f];
            acch += i1;
            av0  += i2*uq.x + i0*vj.x;
            av1  += i2*uq.y + i0*vj.y;
            av2  += i2*uq.z + i0*vj.z;
        }
        g_h[nxt][i*FDIM+f] = g_h[cur][i*FDIM+f] + 0.5f*acch;
        float4 vc = vcur[i*FDIM+f];
        g_v[nxt][i*FDIM+f] = make_float4(vc.x + 0.5f*av0, vc.y + 0.5f*av1, vc.z + 0.5f*av2, 0.f);
    } else {
        int q  = blockIdx.x - BN;
        int ib = q & 31;
        int b  = ib >> 4;
        int cg0 = (ib & 15) << 2;
        int a0 = (q >> 5) << 4;
        int f  = threadIdx.x;
        const float2* Tc = g_Tcon2 + (size_t)tc*PCON*384;
        const float4* vbuf = g_v[cur];
        float cx[4], cy[4], cz[4];
        #pragma unroll
        for (int c = 0; c < 4; c++) {
            int base = (b*NCGC + cg0 + c)*3;
            cx[c] = cgxyz[base]; cy[c] = cgxyz[base+1]; cz[c] = cgxyz[base+2];
        }
        float bf0 = bf[f*3+0], bf1 = bf[f*3+1], bf2 = bf[f*3+2];
        const float inv_step = (PCON-1)/DMAXC;
        float hacc[4], v0a[4], v1a[4], v2a[4];
        #pragma unroll
        for (int c = 0; c < 4; c++) { hacc[c]=0.f; v0a[c]=0.f; v1a[c]=0.f; v2a[c]=0.f; }
        for (int aa = 0; aa < 16; aa++) {
            int n = b*NNODES + a0 + aa;
            float px = xyz[3*n], py = xyz[3*n+1], pz = xyz[3*n+2];
            const float* pp = g_phic + n*384;
            float f0 = pp[f], f1 = pp[128+f], f2 = pp[256+f];
            float4 vp = vbuf[n*FDIM + f];
            const float* as = assign + n*NCGC + cg0;
            #pragma unroll
            for (int c = 0; c < 4; c++) {
                float rx = px - cx[c], ry = py - cy[c], rz = pz - cz[c];
                float d = sqrtf(rx*rx + ry*ry + rz*rz);
                float inv_d = 1.f/d;
                float s = as[c];
                float td = d*inv_step;
                int idx = (int)td;
                float fr;
                if (idx > PCON-2) { idx = PCON-2; fr = 1.f; } else fr = td - idx;
                const float2* ba = Tc + idx*384;
                float2 q0 = ba[f], q1 = ba[128+f], q2 = ba[256+f];
                float w0 = fmaf(fr, q0.y - q0.x, q0.x) + bf0;
                float w1 = fmaf(fr, q1.y - q1.x, q1.x) + bf1;
                float w2 = fmaf(fr, q2.y - q2.x, q2.x) + bf2;
                float x0 = w0*f0, x1 = w1*f1, x2 = w2*f2;
                hacc[c] += s*x1;
                v0a[c]  += s*(x2*(rx*inv_d) + x0*vp.x);
                v1a[c]  += s*(x2*(ry*inv_d) + x0*vp.y);
                v2a[c]  += s*(x2*(rz*inv_d) + x0*vp.z);
            }
        }
        #pragma unroll
        for (int c = 0; c < 4; c++) {
            int cc = b*NCGC + cg0 + c;
            atomicAdd(&out[cc*FDIM + f], hacc[c]);
            float* vout = out + BB*NCGC*FDIM + (cc*FDIM + f)*3;
            atomicAdd(vout+0, v0a[c]);
            atomicAdd(vout+1, v1a[c]);
            atomicAdd(vout+2, v2a[c]);
        }
    }
}

// ---------------- final standalone contract (8-atom chunks, 2048 blocks) ----------------
__global__ void __launch_bounds__(128) k_contract(int t, int buf,
    const float* __restrict__ bf,
    const float* __restrict__ xyz, const float* __restrict__ cgxyz,
    const float* __restrict__ assign, float* __restrict__ out)
{
    int f  = threadIdx.x;
    int b  = blockIdx.x >> 4;
    int cg0 = (blockIdx.x & 15) << 2;
    int a0 = blockIdx.y << 3;                 // 8 atoms per chunk, gridDim.y = 64
    const float2* Tc = g_Tcon2 + (size_t)t*PCON*384;
    const float4* vbuf = g_v[buf];
    float cx[4], cy[4], cz[4];
    #pragma unroll
    for (int c = 0; c < 4; c++) {
        int base = (b*NCGC + cg0 + c)*3;
        cx[c] = cgxyz[base]; cy[c] = cgxyz[base+1]; cz[c] = cgxyz[base+2];
    }
    float bf0 = bf[f*3+0], bf1 = bf[f*3+1], bf2 = bf[f*3+2];
    const float inv_step = (PCON-1)/DMAXC;
    float hacc[4], v0a[4], v1a[4], v2a[4];
    #pragma unroll
    for (int c = 0; c < 4; c++) { hacc[c]=0.f; v0a[c]=0.f; v1a[c]=0.f; v2a[c]=0.f; }
    for (int aa = 0; aa < 8; aa++) {
        int n = b*NNODES + a0 + aa;
        float px = xyz[3*n], py = xyz[3*n+1], pz = xyz[3*n+2];
        const float* pp = g_phic + n*384;
        float f0 = pp[f], f1 = pp[128+f], f2 = pp[256+f];
        float4 vp = vbuf[n*FDIM + f];
        const float* as = assign + n*NCGC + cg0;
        #pragma unroll
        for (int c = 0; c < 4; c++) {
            float rx = px - cx[c], ry = py - cy[c], rz = pz - cz[c];
            float d = sqrtf(rx*rx + ry*ry + rz*rz);
            float inv_d = 1.f/d;
            float s = as[c];
            float td = d*inv_step;
            int idx = (int)td;
            float fr;
            if (idx > PCON-2) { idx = PCON-2; fr = 1.f; } else fr = td - idx;
            const float2* ba = Tc + idx*384;
            float2 q0 = ba[f], q1 = ba[128+f], q2 = ba[256+f];
            float w0 = fmaf(fr, q0.y - q0.x, q0.x) + bf0;
            float w1 = fmaf(fr, q1.y - q1.x, q1.x) + bf1;
            float w2 = fmaf(fr, q2.y - q2.x, q2.x) + bf2;
            float x0 = w0*f0, x1 = w1*f1, x2 = w2*f2;
            hacc[c] += s*x1;
            v0a[c]  += s*(x2*(rx*inv_d) + x0*vp.x);
            v1a[c]  += s*(x2*(ry*inv_d) + x0*vp.y);
            v2a[c]  += s*(x2*(rz*inv_d) + x0*vp.z);
        }
    }
    #pragma unroll
    for (int c = 0; c < 4; c++) {
        int cc = b*NCGC + cg0 + c;
        atomicAdd(&out[cc*FDIM + f], hacc[c]);
        float* vout = out + BB*NCGC*FDIM + (cc*FDIM + f)*3;
        atomicAdd(vout+0, v0a[c]);
        atomicAdd(vout+1, v1a[c]);
        atomicAdd(vout+2, v2a[c]);
    }
}

// ---------------- FUSED node kernel: 11 phases (paired W2 chunks) ----------------
__global__ void __launch_bounds__(512) k_fused(
    const float* __restrict__ U,   const float* __restrict__ Vm,
    const float* __restrict__ uW1, const float* __restrict__ ub1,
    const float* __restrict__ uW2, const float* __restrict__ ub2,
    const float* __restrict__ cW1, const float* __restrict__ cb1,
    const float* __restrict__ cW2, const float* __restrict__ cb2,
    const float* __restrict__ mW1, const float* __restrict__ mb1,
    const float* __restrict__ mW2, const float* __restrict__ mb2,
    int buf, int do_msg)
{
    extern __shared__ float sm[];
    uint32_t smb = (uint32_t)__cvta_generic_to_shared(sm);
    uint32_t sB0 = smb, sB1 = smb + 16384*4, sB2 = smb + 32768*4;
    float*  B0    = sm;
    float*  B1    = sm + 16384;
    float*  B2    = sm + 32768;
    float*  h_s   = sm + 49152;
    float4* v_s   = (float4*)(sm + 50176);
    float*  vn_s  = sm + 54272;
    float*  hid_s = sm + 55296;
    int t = threadIdx.x;
    int g = t & 127, n0 = (t >> 7) * 2;
    int nb = blockIdx.x*8;
    float*  hb = g_h[buf];
    float4* vb = g_v[buf];
    const float4* uW2_4 = (const float4*)uW2;
    const float4* cW2_4 = (const float4*)cW2;
    const float4* mW2_4 = (const float4*)mW2;

    stage64(sB0, (const float4*)U,  t); CP_COMMIT();
    stage64(sB1, (const float4*)Vm, t); CP_COMMIT();
    stage64(sB2, (const float4*)uW1, t); CP_COMMIT();
    for (int i = t; i < 8*FDIM; i += 512) {
        h_s[i] = hb[nb*FDIM + i];
        v_s[i] = vb[nb*FDIM + i];
    }

    CP_WAIT(1);
    __syncthreads();
    float au0[3] = {0.f,0.f,0.f}, au1[3] = {0.f,0.f,0.f};
    float av0[3] = {0.f,0.f,0.f}, av1[3] = {0.f,0.f,0.f};
    #pragma unroll 4
    for (int f = 0; f < FDIM; f++) {
        float uu = B0[f*FDIM+g];
        float vv = B1[f*FDIM+g];
        float4 x0 = v_s[n0*FDIM + f];
        float4 x1 = v_s[(n0+1)*FDIM + f];
        au0[0] += x0.x*uu; au0[1] += x0.y*uu; au0[2] += x0.z*uu;
        au1[0] += x1.x*uu; au1[1] += x1.y*uu; au1[2] += x1.z*uu;
        av0[0] += x0.x*vv; av0[1] += x0.y*vv; av0[2] += x0.z*vv;
        av1[0] += x1.x*vv; av1[1] += x1.y*vv; av1[2] += x1.z*vv;
    }
    float dot0 = au0[0]*av0[0] + au0[1]*av0[1] + au0[2]*av0[2];
    float dot1 = au1[0]*av1[0] + au1[1]*av1[1] + au1[2]*av1[2];
    vn_s[n0*FDIM + g]     = sqrtf(av0[0]*av0[0] + av0[1]*av0[1] + av0[2]*av0[2] + 1e-15f);
    vn_s[(n0+1)*FDIM + g] = sqrtf(av1[0]*av1[0] + av1[1]*av1[1] + av1[2]*av1[2] + 1e-15f);
    __syncthreads();
    stage64(sB0, ((const float4*)uW1) + 4096, t); CP_COMMIT();
    stageW2(sB1, uW2_4, 0, t);                    CP_COMMIT();

    CP_WAIT(2);
    __syncthreads();
    float ac0 = ub1[g], ac1 = ac0;
    GEMV2(B2, h_s, ac0, ac1)
    __syncthreads();
    stageW2(sB2, uW2_4, 1, t); CP_COMMIT();

    CP_WAIT(2);
    __syncthreads();
    GEMV2(B0, vn_s, ac0, ac1)
    hid_s[n0*FDIM+g]     = silu(ac0);
    hid_s[(n0+1)*FDIM+g] = silu(ac1);
    __syncthreads();
    stageW2(sB0, uW2_4, 2, t); CP_COMMIT();

    float A[3][2];
    CP_WAIT(1);
    __syncthreads();
    {
        float a0 = ub2[g], a1 = a0;
        float c0 = ub2[128+g], c1 = c0;
        GEMV2x2(B1, B2, hid_s, a0, a1, c0, c1)
        A[0][0]=a0; A[0][1]=a1; A[1][0]=c0; A[1][1]=c1;
    }
    __syncthreads();
    stage64(sB1, (const float4*)cW1, t); CP_COMMIT();
    stageW2(sB2, cW2_4, 0, t);           CP_COMMIT();

    CP_WAIT(2);
    __syncthreads();
    { float a0 = ub2[256+g], a1 = a0; GEMV2(B0, hid_s, a0, a1) A[2][0]=a0; A[2][1]=a1; }
    {
        float ds0 = dot0*A[1][0] + A[2][0];
        float ds1 = dot1*A[1][1] + A[2][1];
        float nh0 = h_s[n0*FDIM+g]     + 0.5f*ds0;
        float nh1 = h_s[(n0+1)*FDIM+g] + 0.5f*ds1;
        hb[(nb+n0  )*FDIM + g] = nh0;
        hb[(nb+n0+1)*FDIM + g] = nh1;
        float4 vo0 = v_s[n0*FDIM + g];
        float4 vo1 = v_s[(n0+1)*FDIM + g];
        vb[(nb+n0  )*FDIM + g] = make_float4(vo0.x + 0.5f*A[0][0]*au0[0],
                                             vo0.y + 0.5f*A[0][0]*au0[1],
                                             vo0.z + 0.5f*A[0][0]*au0[2], 0.f);
        vb[(nb+n0+1)*FDIM + g] = make_float4(vo1.x + 0.5f*A[0][1]*au1[0],
                                             vo1.y + 0.5f*A[0][1]*au1[1],
                                             vo1.z + 0.5f*A[0][1]*au1[2], 0.f);
        h_s[n0*FDIM+g]     = nh0;
        h_s[(n0+1)*FDIM+g] = nh1;
    }
    __syncthreads();
    stageW2(sB0, cW2_4, 1, t); CP_COMMIT();

    CP_WAIT(2);
    __syncthreads();
    { float a0 = cb1[g], a1 = a0; GEMV2(B1, h_s, a0, a1)
      hid_s[n0*FDIM+g] = silu(a0); hid_s[(n0+1)*FDIM+g] = silu(a1); }
    __syncthreads();
    stageW2(sB1, cW2_4, 2, t); CP_COMMIT();

    CP_WAIT(1);
    __syncthreads();
    {
        float a0 = cb2[g], a1 = a0;
        float c0 = cb2[128+g], c1 = c0;
        GEMV2x2(B2, B0, hid_s, a0, a1, c0, c1)
        A[0][0]=a0; A[0][1]=a1; A[1][0]=c0; A[1][1]=c1;
    }
    __syncthreads();
    stage64(sB2, (const float4*)mW1, t); CP_COMMIT();
    stageW2(sB0, mW2_4, 0, t);           CP_COMMIT();

    CP_WAIT(2);
    __syncthreads();
    { float a0 = cb2[256+g], a1 = a0; GEMV2(B1, hid_s, a0, a1) A[2][0]=a0; A[2][1]=a1; }
    #pragma unroll
    for (int mm = 0; mm < 3; mm++) {
        int m = mm*128 + g;
        int oi = ((m % 3) << 7) + (m / 3);
        g_phic[(nb+n0  )*384 + oi] = A[mm][0];
        g_phic[(nb+n0+1)*384 + oi] = A[mm][1];
    }
    __syncthreads();
    stageW2(sB1, mW2_4, 1, t); CP_COMMIT();

    CP_WAIT(2);
    __syncthreads();
    { float a0 = mb1[g], a1 = a0; GEMV2(B2, h_s, a0, a1)
      hid_s[n0*FDIM+g] = silu(a0); hid_s[(n0+1)*FDIM+g] = silu(a1); }
    __syncthreads();
    stageW2(sB2, mW2_4, 2, t); CP_COMMIT();

    CP_WAIT(1);
    __syncthreads();
    {
        float a0 = mb2[g], a1 = a0;
        float c0 = mb2[128+g], c1 = c0;
        GEMV2x2(B0, B1, hid_s, a0, a1, c0, c1)
        A[0][0]=a0; A[0][1]=a1; A[1][0]=c0; A[1][1]=c1;
    }

    CP_WAIT(0);
    __syncthreads();
    { float a0 = mb2[256+g], a1 = a0; GEMV2(B2, hid_s, a0, a1) A[2][0]=a0; A[2][1]=a1; }
    if (do_msg) {
        g_phi4[(nb+n0  )*FDIM + g] = make_float4(A[0][0], A[1][0], A[2][0], 0.f);
        g_phi4[(nb+n0+1)*FDIM + g] = make_float4(A[0][1], A[1][1], A[2][1], 0.f);
    }
}

// ---------------- host ----------------
#define MLP_SMEM (204800)
#define FUS_SMEM (225280)

extern "C" void kernel_launch(void* const* d_in, const int* in_sizes, int n_in,
                              void* d_out, int out_size)
{
    const float* h_in   = (const float*)d_in[0];
    const float* H_in   = (const float*)d_in[1];
    const float* xyz    = (const float*)d_in[2];
    const float* cgxyz  = (const float*)d_in[3];
    const float* assign = (const float*)d_in[4];
    const int*   nbr    = (const int*)  d_in[6];
    const float* msgW1  = (const float*)d_in[7];
    const float* msgb1  = (const float*)d_in[8];
    const float* msgW2  = (const float*)d_in[9];
    const float* msgb2  = (const float*)d_in[10];
    const float* We     = (const float*)d_in[11];
    const float* be     = (const float*)d_in[12];
    const float* updU   = (const float*)d_in[13];
    const float* updV   = (const float*)d_in[14];
    const float* updW1  = (const float*)d_in[15];
    const float* updb1  = (const float*)d_in[16];
    const float* updW2  = (const float*)d_in[17];
    const float* updb2  = (const float*)d_in[18];
    const float* conWf  = (const float*)d_in[19];
    const float* conbf  = (const float*)d_in[20];
    const float* conW1  = (const float*)d_in[21];
    const float* conb1  = (const float*)d_in[22];
    const float* conW2  = (const float*)d_in[23];
    const float* conb2  = (const float*)d_in[24];
    float* out = (float*)d_out;

    cudaFuncSetAttribute(k_mlp,   cudaFuncAttributeMaxDynamicSharedMemorySize, MLP_SMEM);
    cudaFuncSetAttribute(k_fused, cudaFuncAttributeMaxDynamicSharedMemorySize, FUS_SMEM);

    k_init_geom<<<ETOT/256, 256>>>(h_in, H_in, out, nbr, xyz);          // 1
    k_count<<<ETOT/256, 256>>>();                                        // 2
    k_scan<<<1, BN>>>();                                                 // 3
    k_mlp<<<BN/8, 512, MLP_SMEM>>>(0, msgW1, msgb1, msgW2, msgb2, 0);    // 4 (profiled)
    k_fill<<<ETOT/256, 256>>>();                                         // 5
    {
        dim3 gm(PMSG, NCONVS);
        k_msg_table<<<gm, 128>>>(We, be);                                // 6
        dim3 gc(PCON/16, NCONVS);
        k_con_table<<<gc, 384>>>(conWf);                                 // 7
    }

    int cur = 0;
    for (int t = 0; t < NCONVS; t++) {
        int nxt = 1 - cur;
        if (t == 0) {
            k_edge_con<<<BN, 128>>>(t, cur, nxt, 0, conbf, xyz, cgxyz, assign, out);
        } else {
            k_edge_con<<<2*BN, 128>>>(t, cur, nxt, t-1, conbf + (t-1)*384,
                                      xyz, cgxyz, assign, out);
        }
        int tm = (t + 1 < NCONVS) ? (t + 1) : 0;
        k_fused<<<BN/8, 512, FUS_SMEM>>>(
            updU + t*FDIM*FDIM, updV + t*FDIM*FDIM,
            updW1 + t*2*FDIM*FDIM, updb1 + t*FDIM,
            updW2 + t*FDIM*384,    updb2 + t*384,
            conW1 + t*FDIM*FDIM,   conb1 + t*FDIM,
            conW2 + t*FDIM*384,    conb2 + t*384,
            msgW1 + tm*FDIM*FDIM,  msgb1 + tm*FDIM,
            msgW2 + tm*FDIM*384,   msgb2 + tm*384,
            nxt, (t + 1 < NCONVS) ? 1 : 0);
        cur = nxt;
    }
    {
        dim3 gk(BB*NCGC/4, 64);
        k_contract<<<gk, 128>>>(NCONVS-1, cur, conbf + (NCONVS-1)*384,
                                xyz, cgxyz, assign, out);
    }
    (void)in_sizes; (void)n_in; (void)out_size;
}

// round 16
// speedup vs baseline: 1.3670x; 1.0799x over previous
#include <cuda_runtime.h>
#include <math.h>
#include <stdint.h>

#define BB      2
#define NNODES  512
#define NCGC    64
#define FDIM    128
#define NRBF    20
#define NCONVS  3
#define ETOT    32768
#define BN      (BB*NNODES)      // 1024
#define CUT     5.0f
#define PI_F    3.14159265358979323846f
#define PMSG    4096
#define PCON    1024
#define DMAXC   10.0f

// ---------------- persistent device scratch ----------------
__device__ float  g_h[2][BN*FDIM];
__device__ float4 g_v[2][BN*FDIM];
__device__ float4 g_phi4[BN*FDIM];
__device__ float  g_phic[BN*384];
__device__ float4 g_TmsgA[NCONVS*PMSG*FDIM];
__device__ float2 g_TmsgB[NCONVS*PMSG*FDIM];
__device__ float2 g_Tcon2[NCONVS*PCON*384];
__device__ float  g_ed[ETOT];
__device__ float4 g_un[ETOT];
__device__ int    g_pi[ETOT], g_pj[ETOT];
__device__ int    g_cnt[BN], g_fill[BN], g_ptrn[BN+1];   // zero-initialized at load; re-zeroed by final k_contract
__device__ int    g_csr[ETOT];

__device__ __forceinline__ float silu(float x) { return x / (1.f + expf(-x)); }

#define CP_COMMIT() asm volatile("cp.async.commit_group;" ::: "memory")
#define CP_WAIT(n)  asm volatile("cp.async.wait_group %0;" :: "n"(n) : "memory")

__device__ __forceinline__ void stage64(uint32_t sdst, const float4* __restrict__ src, int t)
{
    #pragma unroll
    for (int j = 0; j < 8; j++) {
        int i = t + j*512;
        asm volatile("cp.async.cg.shared.global [%0], [%1], 16;"
                     :: "r"(sdst + i*16), "l"(src + i) : "memory");
    }
}
__device__ __forceinline__ void stageW2(uint32_t sdst, const float4* __restrict__ W2_4, int mm, int t)
{
    #pragma unroll
    for (int j = 0; j < 8; j++) {
        int i = t + j*512;
        int k = i >> 5, c = i & 31;
        asm volatile("cp.async.cg.shared.global [%0], [%1], 16;"
                     :: "r"(sdst + i*16), "l"(W2_4 + k*96 + mm*32 + c) : "memory");
    }
}

#define GEMV2(BUF, IN, a0, a1) \
    _Pragma("unroll 8") \
    for (int k_ = 0; k_ < FDIM; k_ += 4) { \
        float4 h0_ = *(const float4*)&IN[n0*FDIM + k_]; \
        float4 h1_ = *(const float4*)&IN[(n0+1)*FDIM + k_]; \
        float w0_ = BUF[k_*FDIM+g], w1_ = BUF[(k_+1)*FDIM+g]; \
        float w2_ = BUF[(k_+2)*FDIM+g], w3_ = BUF[(k_+3)*FDIM+g]; \
        a0 += h0_.x*w0_ + h0_.y*w1_ + h0_.z*w2_ + h0_.w*w3_; \
        a1 += h1_.x*w0_ + h1_.y*w1_ + h1_.z*w2_ + h1_.w*w3_; \
    }

#define GEMV2x2(BUFa, BUFb, IN, a0, a1, c0, c1) \
    _Pragma("unroll 4") \
    for (int k_ = 0; k_ < FDIM; k_ += 4) { \
        float4 h0_ = *(const float4*)&IN[n0*FDIM + k_]; \
        float4 h1_ = *(const float4*)&IN[(n0+1)*FDIM + k_]; \
        float p0_ = BUFa[k_*FDIM+g], p1_ = BUFa[(k_+1)*FDIM+g]; \
        float p2_ = BUFa[(k_+2)*FDIM+g], p3_ = BUFa[(k_+3)*FDIM+g]; \
        float q0_ = BUFb[k_*FDIM+g], q1_ = BUFb[(k_+1)*FDIM+g]; \
        float q2_ = BUFb[(k_+2)*FDIM+g], q3_ = BUFb[(k_+3)*FDIM+g]; \
        a0 += h0_.x*p0_ + h0_.y*p1_ + h0_.z*p2_ + h0_.w*p3_; \
        a1 += h1_.x*p0_ + h1_.y*p1_ + h1_.z*p2_ + h1_.w*p3_; \
        c0 += h0_.x*q0_ + h0_.y*q1_ + h0_.z*q2_ + h0_.w*q3_; \
        c1 += h1_.x*q0_ + h1_.y*q1_ + h1_.z*q2_ + h1_.w*q3_; \
    }

// ---------------- init (h/v/out) + edge geometry + degree count (g_cnt pre-zeroed) ----------------
__global__ void k_init_geom(const float* __restrict__ h_in, const float* __restrict__ H_in,
                            float* __restrict__ out,
                            const int* __restrict__ nbr, const float* __restrict__ xyz)
{
    int idx = blockIdx.x*blockDim.x + threadIdx.x;
    {
        int e = idx;
        int b  = nbr[3*e], ii = nbr[3*e+1], jj = nbr[3*e+2];
        int pi = b*NNODES + ii, pj = b*NNODES + jj;
        g_pi[e] = pi; g_pj[e] = pj;
        float rx = xyz[3*pi]   - xyz[3*pj];
        float ry = xyz[3*pi+1] - xyz[3*pj+1];
        float rz = xyz[3*pi+2] - xyz[3*pj+2];
        float d = sqrtf(rx*rx + ry*ry + rz*rz);
        g_ed[e] = d;
        float inv = 1.f/d;
        g_un[e] = make_float4(rx*inv, ry*inv, rz*inv, 0.f);
        if (d < CUT) atomicAdd(&g_cnt[pi], 1);
    }
    for (int i = idx; i < BN*FDIM; i += ETOT) {
        g_h[0][i] = h_in[i];
        g_v[0][i] = make_float4(0.f,0.f,0.f,0.f);
    }
    for (int i = idx; i < BB*NCGC*FDIM*4; i += ETOT)
        out[i] = (i < BB*NCGC*FDIM) ? H_in[i] : 0.f;
}

// ---------------- 1-block exclusive scan of 1024 degrees ----------------
__global__ void k_scan()
{
    __shared__ int s[BN];
    int t = threadIdx.x;   // 1024
    s[t] = g_cnt[t];
    __syncthreads();
    for (int off = 1; off < BN; off <<= 1) {
        int x = (t >= off) ? s[t-off] : 0;
        __syncthreads();
        s[t] += x;
        __syncthreads();
    }
    g_ptrn[t+1] = s[t];
    if (t == 0) g_ptrn[0] = 0;
}

// ---------------- mega setup: CSR fill + con_table + msg_table in one launch (384 thr) ----------------
// blocks [0,128): fill | [128,320): con_table | [320, 320+4096): msg_table (3 (p,t) units/block)
#define SET_FILL  128
#define SET_CON   192
#define SET_MSG   4096
__global__ void __launch_bounds__(384) k_setup(const float* __restrict__ We, const float* __restrict__ be,
                                               const float* __restrict__ Wf)
{
    int b = blockIdx.x;
    int tid = threadIdx.x;
    if (b < SET_FILL) {
        int i = b*384 + tid;
        if (i < ETOT && g_ed[i] < CUT) {
            int pi = g_pi[i];
            int pos = g_ptrn[pi] + atomicAdd(&g_fill[pi], 1);
            g_csr[pos] = i;
        }
    } else if (b < SET_FILL + SET_CON) {
        __shared__ float es[17][FDIM];
        int idx = b - SET_FILL;
        int p0  = (idx & 63)*16, t = idx >> 6;
        const float step = DMAXC/(PCON-1);
        for (int i = tid; i < 17*FDIM; i += 384) {
            int pl = i / FDIM, k = i % FDIM;
            float d = (p0+pl)*step;
            float o = CUT*k/127.f;
            float x = d - o;
            es[pl][k] = expf(-x*x);
        }
        __syncthreads();
        int src = (tid & 127)*3 + (tid >> 7);
        float acc[17];
        #pragma unroll
        for (int p = 0; p < 17; p++) acc[p] = 0.f;
        const float* Wt = Wf + t*FDIM*384;
        for (int k = 0; k < FDIM; k++) {
            float w = Wt[k*384 + src];
            #pragma unroll
            for (int p = 0; p < 17; p++) acc[p] += es[p][k]*w;
        }
        #pragma unroll
        for (int p = 0; p < 16; p++)
            g_Tcon2[(t*PCON + p0 + p)*384 + tid] = make_float2(acc[p], acc[p+1]);
    } else {
        // msg table: unit = (b-320)*3 + sub;  p = unit % PMSG, t = unit / PMSG
        __shared__ float rb[3][2][NRBF];
        int sub = tid >> 7, f = tid & 127;
        int unit = (b - SET_FILL - SET_CON)*3 + sub;
        int p = unit & (PMSG-1), t = unit >> 12;
        const float step = CUT/(PMSG-1);
        float d0 = p*step;
        int p1i = (p+1 < PMSG) ? p+1 : PMSG-1;
        float d1 = p1i*step;
        float env0 = (d0 < CUT) ? 0.5f*(cosf(PI_F*d0/CUT) + 1.f) : 0.f;
        float env1 = (d1 < CUT) ? 0.5f*(cosf(PI_F*d1/CUT) + 1.f) : 0.f;
        if (f < 2*NRBF) {
            int which = f/NRBF, k = f%NRBF;
            float d = which ? d1 : d0;
            float dd = fmaxf(d, 1e-6f);
            rb[sub][which][k] = sinf((k+1)*PI_F/CUT*dd)/dd;
        }
        __syncthreads();
        const float* Wt = We + t*NRBF*384;
        const float* bt = be + t*384;
        float b0 = bt[f], b1 = bt[128+f], b2 = bt[256+f];
        float w0p0=b0, w0p1=b0, w1p0=b1, w1p1=b1, w2p0=b2, w2p1=b2;
        #pragma unroll
        for (int k = 0; k < NRBF; k++) {
            float wa = Wt[k*384+f], wb = Wt[k*384+128+f], wc = Wt[k*384+256+f];
            float r0 = rb[sub][0][k], r1 = rb[sub][1][k];
            w0p0 += r0*wa; w0p1 += r1*wa;
            w1p0 += r0*wb; w1p1 += r1*wb;
            w2p0 += r0*wc; w2p1 += r1*wc;
        }
        int o = (t*PMSG+p)*FDIM + f;
        g_TmsgA[o] = make_float4(w0p0*env0, w0p1*env1, w1p0*env0, w1p1*env1);
        g_TmsgB[o] = make_float2(w2p0*env0, w2p1*env1);
    }
}

// ---------------- standalone MLP (msg t=0), paired W2 c0+c1 ----------------
__global__ void __launch_bounds__(512) k_mlp(int hsel,
                      const float* __restrict__ W1, const float* __restrict__ b1,
                      const float* __restrict__ W2, const float* __restrict__ b2, int dst_sel)
{
    extern __shared__ float sm[];
    uint32_t smb = (uint32_t)__cvta_generic_to_shared(sm);
    float* wsW1  = sm;
    float* bufA  = sm + 16384;
    float* bufB  = sm + 32768;
    float* h_s   = sm + 49152;
    float* hid_s = sm + 50176;
    int t = threadIdx.x;
    int nb = blockIdx.x*8;
    const float4* W2_4 = (const float4*)W2;

    stage64(smb,            (const float4*)W1, t); CP_COMMIT();
    stageW2(smb + 16384*4,  W2_4, 0, t);           CP_COMMIT();
    stageW2(smb + 32768*4,  W2_4, 1, t);           CP_COMMIT();
    const float* hb = g_h[hsel];
    for (int i = t; i < 8*FDIM; i += 512)
        h_s[i] = hb[nb*FDIM + i];

    CP_WAIT(2);
    __syncthreads();
    int g = t & 127, n0 = (t >> 7) * 2;
    {
        float a0 = b1[g], a1 = a0;
        GEMV2(wsW1, h_s, a0, a1)
        hid_s[n0*FDIM+g]     = silu(a0);
        hid_s[(n0+1)*FDIM+g] = silu(a1);
    }
    float A[3][2];
    CP_WAIT(0);
    __syncthreads();
    {
        float a0 = b2[g], a1 = a0;
        float c0 = b2[128+g], c1 = c0;
        GEMV2x2(bufA, bufB, hid_s, a0, a1, c0, c1)
        A[0][0]=a0; A[0][1]=a1; A[1][0]=c0; A[1][1]=c1;
    }
    __syncthreads();
    stageW2(smb + 16384*4, W2_4, 2, t); CP_COMMIT();
    CP_WAIT(0);
    __syncthreads();
    {
        float a0 = b2[256+g], a1 = a0;
        GEMV2(bufA, hid_s, a0, a1)
        A[2][0] = a0; A[2][1] = a1;
    }
    if (dst_sel == 0) {
        g_phi4[(nb+n0  )*FDIM + g] = make_float4(A[0][0], A[1][0], A[2][0], 0.f);
        g_phi4[(nb+n0+1)*FDIM + g] = make_float4(A[0][1], A[1][1], A[2][1], 0.f);
    } else {
        #pragma unroll
        for (int mm = 0; mm < 3; mm++) {
            int m = mm*128 + g;
            int oi = ((m % 3) << 7) + (m / 3);
            g_phic[(nb+n0  )*384 + oi] = A[mm][0];
            g_phic[(nb+n0+1)*384 + oi] = A[mm][1];
        }
    }
}

// ---------------- merged: edge(t) blocks [0,BN) + contract(t-1) blocks [BN,2BN) ----------------
__global__ void __launch_bounds__(128) k_edge_con(int te, int cur, int nxt,
    int tc, const float* __restrict__ bf,
    const float* __restrict__ xyz, const float* __restrict__ cgxyz,
    const float* __restrict__ assign, float* __restrict__ out)
{
    if (blockIdx.x < BN) {
        int i = blockIdx.x, f = threadIdx.x;
        int e0 = g_ptrn[i], e1 = g_ptrn[i+1];
        const float4* TA = g_TmsgA + (size_t)te*PMSG*FDIM;
        const float2* TB = g_TmsgB + (size_t)te*PMSG*FDIM;
        const float4* vcur = g_v[cur];
        const float inv_step = (PMSG-1)/CUT;
        float acch = 0.f, av0 = 0.f, av1 = 0.f, av2 = 0.f;
        for (int q = e0; q < e1; q++) {
            int e = g_csr[q];
            float d = g_ed[e];
            float u = d*inv_step;
            int idx = (int)u; if (idx > PMSG-2) idx = PMSG-2;
            float fr = u - idx;
            float4 Aq = TA[idx*FDIM + f];
            float2 Bq = TB[idx*FDIM + f];
            float w0 = fmaf(fr, Aq.y - Aq.x, Aq.x);
            float w1 = fmaf(fr, Aq.w - Aq.z, Aq.z);
            float w2 = fmaf(fr, Bq.y - Bq.x, Bq.x);
            int pj = g_pj[e];
            float4 ph = g_phi4[pj*FDIM + f];
            float i0 = ph.x*w0, i1 = ph.y*w1, i2 = ph.z*w2;
            float4 uq = g_un[e];
            float4 vj = vcur[pj*FDIM + f];
            acch += i1;
            av0  += i2*uq.x + i0*vj.x;
            av1  += i2*uq.y + i0*vj.y;
            av2  += i2*uq.z + i0*vj.z;
        }
        g_h[nxt][i*FDIM+f] = g_h[cur][i*FDIM+f] + 0.5f*acch;
        float4 vc = vcur[i*FDIM+f];
        g_v[nxt][i*FDIM+f] = make_float4(vc.x + 0.5f*av0, vc.y + 0.5f*av1, vc.z + 0.5f*av2, 0.f);
    } else {
        int q  = blockIdx.x - BN;
        int ib = q & 31;
        int b  = ib >> 4;
        int cg0 = (ib & 15) << 2;
        int a0 = (q >> 5) << 4;
        int f  = threadIdx.x;
        const float2* Tc = g_Tcon2 + (size_t)tc*PCON*384;
        const float4* vbuf = g_v[cur];
        float cx[4], cy[4], cz[4];
        #pragma unroll
        for (int c = 0; c < 4; c++) {
            int base = (b*NCGC + cg0 + c)*3;
            cx[c] = cgxyz[base]; cy[c] = cgxyz[base+1]; cz[c] = cgxyz[base+2];
        }
        float bf0 = bf[f*3+0], bf1 = bf[f*3+1], bf2 = bf[f*3+2];
        const float inv_step = (PCON-1)/DMAXC;
        float hacc[4], v0a[4], v1a[4], v2a[4];
        #pragma unroll
        for (int c = 0; c < 4; c++) { hacc[c]=0.f; v0a[c]=0.f; v1a[c]=0.f; v2a[c]=0.f; }
        for (int aa = 0; aa < 16; aa++) {
            int n = b*NNODES + a0 + aa;
            float px = xyz[3*n], py = xyz[3*n+1], pz = xyz[3*n+2];
            const float* pp = g_phic + n*384;
            float f0 = pp[f], f1 = pp[128+f], f2 = pp[256+f];
            float4 vp = vbuf[n*FDIM + f];
            const float* as = assign + n*NCGC + cg0;
            #pragma unroll
            for (int c = 0; c < 4; c++) {
                float rx = px - cx[c], ry = py - cy[c], rz = pz - cz[c];
                float d = sqrtf(rx*rx + ry*ry + rz*rz);
                float inv_d = 1.f/d;
                float s = as[c];
                float td = d*inv_step;
                int idx = (int)td;
                float fr;
                if (idx > PCON-2) { idx = PCON-2; fr = 1.f; } else fr = td - idx;
                const float2* ba = Tc + idx*384;
                float2 q0 = ba[f], q1 = ba[128+f], q2 = ba[256+f];
                float w0 = fmaf(fr, q0.y - q0.x, q0.x) + bf0;
                float w1 = fmaf(fr, q1.y - q1.x, q1.x) + bf1;
                float w2 = fmaf(fr, q2.y - q2.x, q2.x) + bf2;
                float x0 = w0*f0, x1 = w1*f1, x2 = w2*f2;
                hacc[c] += s*x1;
                v0a[c]  += s*(x2*(rx*inv_d) + x0*vp.x);
                v1a[c]  += s*(x2*(ry*inv_d) + x0*vp.y);
                v2a[c]  += s*(x2*(rz*inv_d) + x0*vp.z);
            }
        }
        #pragma unroll
        for (int c = 0; c < 4; c++) {
            int cc = b*NCGC + cg0 + c;
            atomicAdd(&out[cc*FDIM + f], hacc[c]);
            float* vout = out + BB*NCGC*FDIM + (cc*FDIM + f)*3;
            atomicAdd(vout+0, v0a[c]);
            atomicAdd(vout+1, v1a[c]);
            atomicAdd(vout+2, v2a[c]);
        }
    }
}

// ---------------- final standalone contract (8-atom chunks, 2048 blocks) + counter re-zero ----------------
__global__ void __launch_bounds__(128) k_contract(int t, int buf,
    const float* __restrict__ bf,
    const float* __restrict__ xyz, const float* __restrict__ cgxyz,
    const float* __restrict__ assign, float* __restrict__ out)
{
    int f  = threadIdx.x;
    // designated block re-zeroes CSR counters for the next launch/replay
    if (blockIdx.x == 0 && blockIdx.y == 0) {
        #pragma unroll
        for (int i = f; i < BN; i += 128) { g_cnt[i] = 0; g_fill[i] = 0; }
    }
    int b  = blockIdx.x >> 4;
    int cg0 = (blockIdx.x & 15) << 2;
    int a0 = blockIdx.y << 3;
    const float2* Tc = g_Tcon2 + (size_t)t*PCON*384;
    const float4* vbuf = g_v[buf];
    float cx[4], cy[4], cz[4];
    #pragma unroll
    for (int c = 0; c < 4; c++) {
        int base = (b*NCGC + cg0 + c)*3;
        cx[c] = cgxyz[base]; cy[c] = cgxyz[base+1]; cz[c] = cgxyz[base+2];
    }
    float bf0 = bf[f*3+0], bf1 = bf[f*3+1], bf2 = bf[f*3+2];
    const float inv_step = (PCON-1)/DMAXC;
    float hacc[4], v0a[4], v1a[4], v2a[4];
    #pragma unroll
    for (int c = 0; c < 4; c++) { hacc[c]=0.f; v0a[c]=0.f; v1a[c]=0.f; v2a[c]=0.f; }
    for (int aa = 0; aa < 8; aa++) {
        int n = b*NNODES + a0 + aa;
        float px = xyz[3*n], py = xyz[3*n+1], pz = xyz[3*n+2];
        const float* pp = g_phic + n*384;
        float f0 = pp[f], f1 = pp[128+f], f2 = pp[256+f];
        float4 vp = vbuf[n*FDIM + f];
        const float* as = assign + n*NCGC + cg0;
        #pragma unroll
        for (int c = 0; c < 4; c++) {
            float rx = px - cx[c], ry = py - cy[c], rz = pz - cz[c];
            float d = sqrtf(rx*rx + ry*ry + rz*rz);
            float inv_d = 1.f/d;
            float s = as[c];
            float td = d*inv_step;
            int idx = (int)td;
            float fr;
            if (idx > PCON-2) { idx = PCON-2; fr = 1.f; } else fr = td - idx;
            const float2* ba = Tc + idx*384;
            float2 q0 = ba[f], q1 = ba[128+f], q2 = ba[256+f];
            float w0 = fmaf(fr, q0.y - q0.x, q0.x) + bf0;
            float w1 = fmaf(fr, q1.y - q1.x, q1.x) + bf1;
            float w2 = fmaf(fr, q2.y - q2.x, q2.x) + bf2;
            float x0 = w0*f0, x1 = w1*f1, x2 = w2*f2;
            hacc[c] += s*x1;
            v0a[c]  += s*(x2*(rx*inv_d) + x0*vp.x);
            v1a[c]  += s*(x2*(ry*inv_d) + x0*vp.y);
            v2a[c]  += s*(x2*(rz*inv_d) + x0*vp.z);
        }
    }
    #pragma unroll
    for (int c = 0; c < 4; c++) {
        int cc = b*NCGC + cg0 + c;
        atomicAdd(&out[cc*FDIM + f], hacc[c]);
        float* vout = out + BB*NCGC*FDIM + (cc*FDIM + f)*3;
        atomicAdd(vout+0, v0a[c]);
        atomicAdd(vout+1, v1a[c]);
        atomicAdd(vout+2, v2a[c]);
    }
}

// ---------------- FUSED node kernel: 11 phases (paired W2 chunks) ----------------
__global__ void __launch_bounds__(512) k_fused(
    const float* __restrict__ U,   const float* __restrict__ Vm,
    const float* __restrict__ uW1, const float* __restrict__ ub1,
    const float* __restrict__ uW2, const float* __restrict__ ub2,
    const float* __restrict__ cW1, const float* __restrict__ cb1,
    const float* __restrict__ cW2, const float* __restrict__ cb2,
    const float* __restrict__ mW1, const float* __restrict__ mb1,
    const float* __restrict__ mW2, const float* __restrict__ mb2,
    int buf, int do_msg)
{
    extern __shared__ float sm[];
    uint32_t smb = (uint32_t)__cvta_generic_to_shared(sm);
    uint32_t sB0 = smb, sB1 = smb + 16384*4, sB2 = smb + 32768*4;
    float*  B0    = sm;
    float*  B1    = sm + 16384;
    float*  B2    = sm + 32768;
    float*  h_s   = sm + 49152;
    float4* v_s   = (float4*)(sm + 50176);
    float*  vn_s  = sm + 54272;
    float*  hid_s = sm + 55296;
    int t = threadIdx.x;
    int g = t & 127, n0 = (t >> 7) * 2;
    int nb = blockIdx.x*8;
    float*  hb = g_h[buf];
    float4* vb = g_v[buf];
    const float4* uW2_4 = (const float4*)uW2;
    const float4* cW2_4 = (const float4*)cW2;
    const float4* mW2_4 = (const float4*)mW2;

    stage64(sB0, (const float4*)U,  t); CP_COMMIT();
    stage64(sB1, (const float4*)Vm, t); CP_COMMIT();
    stage64(sB2, (const float4*)uW1, t); CP_COMMIT();
    for (int i = t; i < 8*FDIM; i += 512) {
        h_s[i] = hb[nb*FDIM + i];
        v_s[i] = vb[nb*FDIM + i];
    }

    CP_WAIT(1);
    __syncthreads();
    float au0[3] = {0.f,0.f,0.f}, au1[3] = {0.f,0.f,0.f};
    float av0[3] = {0.f,0.f,0.f}, av1[3] = {0.f,0.f,0.f};
    #pragma unroll 4
    for (int f = 0; f < FDIM; f++) {
        float uu = B0[f*FDIM+g];
        float vv = B1[f*FDIM+g];
        float4 x0 = v_s[n0*FDIM + f];
        float4 x1 = v_s[(n0+1)*FDIM + f];
        au0[0] += x0.x*uu; au0[1] += x0.y*uu; au0[2] += x0.z*uu;
        au1[0] += x1.x*uu; au1[1] += x1.y*uu; au1[2] += x1.z*uu;
        av0[0] += x0.x*vv; av0[1] += x0.y*vv; av0[2] += x0.z*vv;
        av1[0] += x1.x*vv; av1[1] += x1.y*vv; av1[2] += x1.z*vv;
    }
    float dot0 = au0[0]*av0[0] + au0[1]*av0[1] + au0[2]*av0[2];
    float dot1 = au1[0]*av1[0] + au1[1]*av1[1] + au1[2]*av1[2];
    vn_s[n0*FDIM + g]     = sqrtf(av0[0]*av0[0] + av0[1]*av0[1] + av0[2]*av0[2] + 1e-15f);
    vn_s[(n0+1)*FDIM + g] = sqrtf(av1[0]*av1[0] + av1[1]*av1[1] + av1[2]*av1[2] + 1e-15f);
    __syncthreads();
    stage64(sB0, ((const float4*)uW1) + 4096, t); CP_COMMIT();
    stageW2(sB1, uW2_4, 0, t);                    CP_COMMIT();

    CP_WAIT(2);
    __syncthreads();
    float ac0 = ub1[g], ac1 = ac0;
    GEMV2(B2, h_s, ac0, ac1)
    __syncthreads();
    stageW2(sB2, uW2_4, 1, t); CP_COMMIT();

    CP_WAIT(2);
    __syncthreads();
    GEMV2(B0, vn_s, ac0, ac1)
    hid_s[n0*FDIM+g]     = silu(ac0);
    hid_s[(n0+1)*FDIM+g] = silu(ac1);
    __syncthreads();
    stageW2(sB0, uW2_4, 2, t); CP_COMMIT();

    float A[3][2];
    CP_WAIT(1);
    __syncthreads();
    {
        float a0 = ub2[g], a1 = a0;
        float c0 = ub2[128+g], c1 = c0;
        GEMV2x2(B1, B2, hid_s, a0, a1, c0, c1)
        A[0][0]=a0; A[0][1]=a1; A[1][0]=c0; A[1][1]=c1;
    }
    __syncthreads();
    stage64(sB1, (const float4*)cW1, t); CP_COMMIT();
    stageW2(sB2, cW2_4, 0, t);           CP_COMMIT();

    CP_WAIT(2);
    __syncthreads();
    { float a0 = ub2[256+g], a1 = a0; GEMV2(B0, hid_s, a0, a1) A[2][0]=a0; A[2][1]=a1; }
    {
        float ds0 = dot0*A[1][0] + A[2][0];
        float ds1 = dot1*A[1][1] + A[2][1];
        float nh0 = h_s[n0*FDIM+g]     + 0.5f*ds0;
        float nh1 = h_s[(n0+1)*FDIM+g] + 0.5f*ds1;
        hb[(nb+n0  )*FDIM + g] = nh0;
        hb[(nb+n0+1)*FDIM + g] = nh1;
        float4 vo0 = v_s[n0*FDIM + g];
        float4 vo1 = v_s[(n0+1)*FDIM + g];
        vb[(nb+n0  )*FDIM + g] = make_float4(vo0.x + 0.5f*A[0][0]*au0[0],
                                             vo0.y + 0.5f*A[0][0]*au0[1],
                                             vo0.z + 0.5f*A[0][0]*au0[2], 0.f);
        vb[(nb+n0+1)*FDIM + g] = make_float4(vo1.x + 0.5f*A[0][1]*au1[0],
                                             vo1.y + 0.5f*A[0][1]*au1[1],
                                             vo1.z + 0.5f*A[0][1]*au1[2], 0.f);
        h_s[n0*FDIM+g]     = nh0;
        h_s[(n0+1)*FDIM+g] = nh1;
    }
    __syncthreads();
    stageW2(sB0, cW2_4, 1, t); CP_COMMIT();

    CP_WAIT(2);
    __syncthreads();
    { float a0 = cb1[g], a1 = a0; GEMV2(B1, h_s, a0, a1)
      hid_s[n0*FDIM+g] = silu(a0); hid_s[(n0+1)*FDIM+g] = silu(a1); }
    __syncthreads();
    stageW2(sB1, cW2_4, 2, t); CP_COMMIT();

    CP_WAIT(1);
    __syncthreads();
    {
        float a0 = cb2[g], a1 = a0;
        float c0 = cb2[128+g], c1 = c0;
        GEMV2x2(B2, B0, hid_s, a0, a1, c0, c1)
        A[0][0]=a0; A[0][1]=a1; A[1][0]=c0; A[1][1]=c1;
    }
    __syncthreads();
    stage64(sB2, (const float4*)mW1, t); CP_COMMIT();
    stageW2(sB0, mW2_4, 0, t);           CP_COMMIT();

    CP_WAIT(2);
    __syncthreads();
    { float a0 = cb2[256+g], a1 = a0; GEMV2(B1, hid_s, a0, a1) A[2][0]=a0; A[2][1]=a1; }
    #pragma unroll
    for (int mm = 0; mm < 3; mm++) {
        int m = mm*128 + g;
        int oi = ((m % 3) << 7) + (m / 3);
        g_phic[(nb+n0  )*384 + oi] = A[mm][0];
        g_phic[(nb+n0+1)*384 + oi] = A[mm][1];
    }
    __syncthreads();
    stageW2(sB1, mW2_4, 1, t); CP_COMMIT();

    CP_WAIT(2);
    __syncthreads();
    { float a0 = mb1[g], a1 = a0; GEMV2(B2, h_s, a0, a1)
      hid_s[n0*FDIM+g] = silu(a0); hid_s[(n0+1)*FDIM+g] = silu(a1); }
    __syncthreads();
    stageW2(sB2, mW2_4, 2, t); CP_COMMIT();

    CP_WAIT(1);
    __syncthreads();
    {
        float a0 = mb2[g], a1 = a0;
        float c0 = mb2[128+g], c1 = c0;
        GEMV2x2(B0, B1, hid_s, a0, a1, c0, c1)
        A[0][0]=a0; A[0][1]=a1; A[1][0]=c0; A[1][1]=c1;
    }

    CP_WAIT(0);
    __syncthreads();
    { float a0 = mb2[256+g], a1 = a0; GEMV2(B2, hid_s, a0, a1) A[2][0]=a0; A[2][1]=a1; }
    if (do_msg) {
        g_phi4[(nb+n0  )*FDIM + g] = make_float4(A[0][0], A[1][0], A[2][0], 0.f);
        g_phi4[(nb+n0+1)*FDIM + g] = make_float4(A[0][1], A[1][1], A[2][1], 0.f);
    }
}

// ---------------- host ----------------
#define MLP_SMEM (204800)
#define FUS_SMEM (225280)

extern "C" void kernel_launch(void* const* d_in, const int* in_sizes, int n_in,
                              void* d_out, int out_size)
{
    const float* h_in   = (const float*)d_in[0];
    const float* H_in   = (const float*)d_in[1];
    const float* xyz    = (const float*)d_in[2];
    const float* cgxyz  = (const float*)d_in[3];
    const float* assign = (const float*)d_in[4];
    const int*   nbr    = (const int*)  d_in[6];
    const float* msgW1  = (const float*)d_in[7];
    const float* msgb1  = (const float*)d_in[8];
    const float* msgW2  = (const float*)d_in[9];
    const float* msgb2  = (const float*)d_in[10];
    const float* We     = (const float*)d_in[11];
    const float* be     = (const float*)d_in[12];
    const float* updU   = (const float*)d_in[13];
    const float* updV   = (const float*)d_in[14];
    const float* updW1  = (const float*)d_in[15];
    const float* updb1  = (const float*)d_in[16];
    const float* updW2  = (const float*)d_in[17];
    const float* updb2  = (const float*)d_in[18];
    const float* conWf  = (const float*)d_in[19];
    const float* conbf  = (const float*)d_in[20];
    const float* conW1  = (const float*)d_in[21];
    const float* conb1  = (const float*)d_in[22];
    const float* conW2  = (const float*)d_in[23];
    const float* conb2  = (const float*)d_in[24];
    float* out = (float*)d_out;

    cudaFuncSetAttribute(k_mlp,   cudaFuncAttributeMaxDynamicSharedMemorySize, MLP_SMEM);
    cudaFuncSetAttribute(k_fused, cudaFuncAttributeMaxDynamicSharedMemorySize, FUS_SMEM);

    k_init_geom<<<ETOT/256, 256>>>(h_in, H_in, out, nbr, xyz);               // 1
    k_scan<<<1, BN>>>();                                                      // 2
    k_setup<<<SET_FILL + SET_CON + SET_MSG, 384>>>(We, be, conWf);            // 3
    k_mlp<<<BN/8, 512, MLP_SMEM>>>(0, msgW1, msgb1, msgW2, msgb2, 0);         // 4 (profiled)

    int cur = 0;
    for (int t = 0; t < NCONVS; t++) {
        int nxt = 1 - cur;
        if (t == 0) {
            k_edge_con<<<BN, 128>>>(t, cur, nxt, 0, conbf, xyz, cgxyz, assign, out);
        } else {
            k_edge_con<<<2*BN, 128>>>(t, cur, nxt, t-1, conbf + (t-1)*384,
                                      xyz, cgxyz, assign, out);
        }
        int tm = (t + 1 < NCONVS) ? (t + 1) : 0;
        k_fused<<<BN/8, 512, FUS_SMEM>>>(
            updU + t*FDIM*FDIM, updV + t*FDIM*FDIM,
            updW1 + t*2*FDIM*FDIM, updb1 + t*FDIM,
            updW2 + t*FDIM*384,    updb2 + t*384,
            conW1 + t*FDIM*FDIM,   conb1 + t*FDIM,
            conW2 + t*FDIM*384,    conb2 + t*384,
            msgW1 + tm*FDIM*FDIM,  msgb1 + tm*FDIM,
            msgW2 + tm*FDIM*384,   msgb2 + tm*384,
            nxt, (t + 1 < NCONVS) ? 1 : 0);
        cur = nxt;
    }
    {
        dim3 gk(BB*NCGC/4, 64);
        k_contract<<<gk, 128>>>(NCONVS-1, cur, conbf + (NCONVS-1)*384,
                                xyz, cgxyz, assign, out);
    }
    (void)in_sizes; (void)n_in; (void)out_size;
}